// round 2
// baseline (speedup 1.0000x reference)
#include <cuda_runtime.h>
#include <math.h>

// Problem constants
#define Bn   64
#define Cn   512
#define Pn   64      // H*W
#define Kn   100
#define H1n  64
#define HIDn 128
#define Ln   32
#define CLIPV 100.0f
#define REDV (-0.1f)
#define PUSHT 10000.0f

#define COLS 128     // columns per CTA (= 2 batch images x 64 positions)
#define KC   64      // C-chunk for GEMM1

// ---- dynamic shared memory layout (floats) ----
// h1 region  : [64][132]   (reused for lt[32][132] + er/er1 arrays in stage 4)
// h2 region  : [128][132]
// misc region: 12800 floats
//   stage1: Wts[64][68] (4352) + Xs[64][132] (8448) = 12800
//   stage2: W2ts[64][132] (8448)
//   stage3: W3ts[128][34] (4352) + protos[2][32][64] (4096)
//   finalize: reduction scratch
#define OFF_H1   0
#define OFF_H2   (64 * 132)                  // 8448
#define OFF_MISC (OFF_H2 + 128 * 132)        // 25344
#define SMEM_FLOATS (OFF_MISC + 12800)       // 38144 floats = 152576 bytes

typedef unsigned long long u64;

__device__ float f_dev[Kn * Bn];
__device__ float f1_dev[Kn * Bn];
__device__ unsigned int done_ctr = 0;

__device__ __forceinline__ u64 fma2(u64 a, u64 b, u64 c) {
    u64 d;
    asm("fma.rn.f32x2 %0, %1, %2, %3;" : "=l"(d) : "l"(a), "l"(b), "l"(c));
    return d;
}
__device__ __forceinline__ u64 bcast2(float a) {
    u64 d;
    asm("mov.b64 %0, {%1, %1};" : "=l"(d) : "f"(a));
    return d;
}
__device__ __forceinline__ float2 unpack2(u64 v) {
    float2 r;
    asm("mov.b64 {%0, %1}, %2;" : "=f"(r.x), "=f"(r.y) : "l"(v));
    return r;
}
__device__ __forceinline__ float tanh_fast(float x) {
    float y;
    asm("tanh.approx.f32 %0, %1;" : "=f"(y) : "f"(x));
    return y;
}

__global__ __launch_bounds__(256, 1)
void fused_cssr(const float* __restrict__ x,
                const int*   __restrict__ ycls,
                const float* __restrict__ W1,
                const float* __restrict__ W2,
                const float* __restrict__ W3,
                const float* __restrict__ pr0,
                const float* __restrict__ pr1,
                float* __restrict__ out)
{
    extern __shared__ float sm[];
    float* h1   = sm + OFF_H1;    // [64][132]
    float* h2   = sm + OFF_H2;    // [128][132]
    float* misc = sm + OFF_MISC;

    const int k    = blockIdx.y;
    const int tile = blockIdx.x;       // 0..31
    const int b0   = tile * 2;         // two batch images per CTA
    const int tid  = threadIdx.x;
    const int tx   = tid & 15;         // 0..15 -> 8-wide column groups
    const int ty   = tid >> 4;         // 0..15 -> row groups

    // =========== Stage 1: h1[64][128] = tanh(W1_k @ X), packed f32x2 ===========
    {
        u64 acc1[4][4];
        #pragma unroll
        for (int i = 0; i < 4; i++)
            #pragma unroll
            for (int j = 0; j < 4; j++) acc1[i][j] = 0ULL;

        float* Wts = misc;             // [64][68] transposed chunk
        float* Xs  = misc + 64 * 68;   // [64][132]
        const float* W1k = W1 + (size_t)k * H1n * Cn;

        for (int c0 = 0; c0 < Cn; c0 += KC) {
            // load W1 chunk (64 rows x 64 c) transposed into Wts[cc][o]
            #pragma unroll
            for (int pass = 0; pass < 4; pass++) {
                int idx = tid + pass * 256;          // 0..1023 float4s
                int o   = idx >> 4;                  // 0..63
                int c4  = (idx & 15) * 4;            // 0..60
                float4 w = *(const float4*)(W1k + (size_t)o * Cn + c0 + c4);
                Wts[(c4 + 0) * 68 + o] = w.x;
                Wts[(c4 + 1) * 68 + o] = w.y;
                Wts[(c4 + 2) * 68 + o] = w.z;
                Wts[(c4 + 3) * 68 + o] = w.w;
            }
            // load X chunk (64 x 128): col j -> (b = b0 + j/64, p = j%64)
            #pragma unroll
            for (int pass = 0; pass < 8; pass++) {
                int idx = tid + pass * 256;          // 0..2047 float4s
                int cc  = idx >> 5;                  // 0..63
                int j4  = (idx & 31) * 4;            // 0..124
                int b   = b0 + (j4 >> 6);
                int p   = j4 & 63;
                float4 v = *(const float4*)(x + ((size_t)b * Cn + (c0 + cc)) * Pn + p);
                *(float4*)(Xs + cc * 132 + j4) = v;
            }
            __syncthreads();
            #pragma unroll 16
            for (int cc = 0; cc < KC; cc++) {
                float4 av = *(float4*)(Wts + cc * 68 + ty * 4);
                ulonglong2 b01 = *(ulonglong2*)(Xs + cc * 132 + tx * 8);
                ulonglong2 b23 = *(ulonglong2*)(Xs + cc * 132 + tx * 8 + 4);
                u64 bp[4] = {b01.x, b01.y, b23.x, b23.y};
                float as[4] = {av.x, av.y, av.z, av.w};
                #pragma unroll
                for (int i = 0; i < 4; i++) {
                    u64 pa = bcast2(as[i]);
                    #pragma unroll
                    for (int j = 0; j < 4; j++) acc1[i][j] = fma2(pa, bp[j], acc1[i][j]);
                }
            }
            __syncthreads();
        }
        // tanh + store h1
        #pragma unroll
        for (int i = 0; i < 4; i++) {
            float2 t0 = unpack2(acc1[i][0]);
            float2 t1 = unpack2(acc1[i][1]);
            float2 t2 = unpack2(acc1[i][2]);
            float2 t3 = unpack2(acc1[i][3]);
            float4 v0 = make_float4(tanh_fast(t0.x), tanh_fast(t0.y), tanh_fast(t1.x), tanh_fast(t1.y));
            float4 v1 = make_float4(tanh_fast(t2.x), tanh_fast(t2.y), tanh_fast(t3.x), tanh_fast(t3.y));
            *(float4*)(h1 + (ty * 4 + i) * 132 + tx * 8)     = v0;
            *(float4*)(h1 + (ty * 4 + i) * 132 + tx * 8 + 4) = v1;
        }
    }
    __syncthreads();

    // =========== Stage 2: h2[128][128] = tanh(W2_k @ h1), packed f32x2 ===========
    {
        float* W2ts = misc;            // [64][132] transposed
        const float* W2k = W2 + (size_t)k * HIDn * H1n;
        #pragma unroll
        for (int pass = 0; pass < 8; pass++) {
            int idx = tid + pass * 256;   // 0..2047 float4s
            int o   = idx >> 4;           // 0..127
            int i4  = (idx & 15) * 4;     // 0..60
            float4 w = *(const float4*)(W2k + (size_t)o * H1n + i4);
            W2ts[(i4 + 0) * 132 + o] = w.x;
            W2ts[(i4 + 1) * 132 + o] = w.y;
            W2ts[(i4 + 2) * 132 + o] = w.z;
            W2ts[(i4 + 3) * 132 + o] = w.w;
        }
        __syncthreads();

        u64 acc2[8][4];
        #pragma unroll
        for (int i = 0; i < 8; i++)
            #pragma unroll
            for (int j = 0; j < 4; j++) acc2[i][j] = 0ULL;

        #pragma unroll 8
        for (int i = 0; i < H1n; i++) {
            float4 av0 = *(float4*)(W2ts + i * 132 + ty * 8);
            float4 av1 = *(float4*)(W2ts + i * 132 + ty * 8 + 4);
            ulonglong2 b01 = *(ulonglong2*)(h1 + i * 132 + tx * 8);
            ulonglong2 b23 = *(ulonglong2*)(h1 + i * 132 + tx * 8 + 4);
            u64 bp[4] = {b01.x, b01.y, b23.x, b23.y};
            float as[8] = {av0.x, av0.y, av0.z, av0.w, av1.x, av1.y, av1.z, av1.w};
            #pragma unroll
            for (int r = 0; r < 8; r++) {
                u64 pa = bcast2(as[r]);
                #pragma unroll
                for (int c = 0; c < 4; c++) acc2[r][c] = fma2(pa, bp[c], acc2[r][c]);
            }
        }
        // tanh + store h2
        #pragma unroll
        for (int r = 0; r < 8; r++) {
            float2 t0 = unpack2(acc2[r][0]);
            float2 t1 = unpack2(acc2[r][1]);
            float2 t2 = unpack2(acc2[r][2]);
            float2 t3 = unpack2(acc2[r][3]);
            float4 v0 = make_float4(tanh_fast(t0.x), tanh_fast(t0.y), tanh_fast(t1.x), tanh_fast(t1.y));
            float4 v1 = make_float4(tanh_fast(t2.x), tanh_fast(t2.y), tanh_fast(t3.x), tanh_fast(t3.y));
            *(float4*)(h2 + (ty * 8 + r) * 132 + tx * 8)     = v0;
            *(float4*)(h2 + (ty * 8 + r) * 132 + tx * 8 + 4) = v1;
        }
    }
    __syncthreads();

    // =========== Stage 3: lt[32][128] = tanh(W3_k @ h2), packed f32x2 ===========
    {
        float* W3ts = misc;              // [128][34] transposed
        float* ps   = misc + 128 * 34;   // [2][32][64] prototypes
        const float* W3k = W3 + (size_t)k * Ln * HIDn;
        #pragma unroll
        for (int pass = 0; pass < 4; pass++) {
            int idx = tid + pass * 256;   // 0..1023 float4s
            int l   = idx >> 5;           // 0..31
            int i4  = (idx & 31) * 4;     // 0..124
            float4 w = *(const float4*)(W3k + (size_t)l * HIDn + i4);
            W3ts[(i4 + 0) * 34 + l] = w.x;
            W3ts[(i4 + 1) * 34 + l] = w.y;
            W3ts[(i4 + 2) * 34 + l] = w.z;
            W3ts[(i4 + 3) * 34 + l] = w.w;
        }
        const float* p0k = pr0 + (size_t)k * Ln * Pn;
        const float* p1k = pr1 + (size_t)k * Ln * Pn;
        #pragma unroll
        for (int pass = 0; pass < 2; pass++) {
            int idx = tid + pass * 256;   // 0..511 float4s per proto
            int e4  = idx * 4;
            *(float4*)(ps + e4)        = *(const float4*)(p0k + e4);
            *(float4*)(ps + 2048 + e4) = *(const float4*)(p1k + e4);
        }
        __syncthreads();

        u64 acc3[2][4];
        #pragma unroll
        for (int i = 0; i < 2; i++)
            #pragma unroll
            for (int j = 0; j < 4; j++) acc3[i][j] = 0ULL;

        #pragma unroll 8
        for (int i = 0; i < HIDn; i++) {
            float a0  = W3ts[i * 34 + ty * 2];
            float a1v = W3ts[i * 34 + ty * 2 + 1];
            ulonglong2 b01 = *(ulonglong2*)(h2 + i * 132 + tx * 8);
            ulonglong2 b23 = *(ulonglong2*)(h2 + i * 132 + tx * 8 + 4);
            u64 bp[4] = {b01.x, b01.y, b23.x, b23.y};
            u64 pa0 = bcast2(a0);
            u64 pa1 = bcast2(a1v);
            #pragma unroll
            for (int c = 0; c < 4; c++) {
                acc3[0][c] = fma2(pa0, bp[c], acc3[0][c]);
                acc3[1][c] = fma2(pa1, bp[c], acc3[1][c]);
            }
        }
        // tanh + store lt into (retired) h1 region
        float* lt = h1;
        #pragma unroll
        for (int r = 0; r < 2; r++) {
            float2 t0 = unpack2(acc3[r][0]);
            float2 t1 = unpack2(acc3[r][1]);
            float2 t2 = unpack2(acc3[r][2]);
            float2 t3 = unpack2(acc3[r][3]);
            float4 v0 = make_float4(tanh_fast(t0.x), tanh_fast(t0.y), tanh_fast(t1.x), tanh_fast(t1.y));
            float4 v1 = make_float4(tanh_fast(t2.x), tanh_fast(t2.y), tanh_fast(t3.x), tanh_fast(t3.y));
            *(float4*)(lt + (ty * 2 + r) * 132 + tx * 8)     = v0;
            *(float4*)(lt + (ty * 2 + r) * 132 + tx * 8 + 4) = v1;
        }
    }
    __syncthreads();

    // =========== Stage 4: distances, er/er1, per-(k,b) sums ===========
    {
        float* lt   = h1;
        float* ps   = misc + 128 * 34;
        float* ers  = h1 + 32 * 132;     // [128]
        float* er1s = ers + 128;         // [128]

        if (tid < COLS) {
            int j = tid;
            int b = b0 + (j >> 6);
            int p = j & 63;
            float d0 = 0.f, d1 = 0.f;
            #pragma unroll
            for (int l = 0; l < Ln; l++) {
                float v  = lt[l * 132 + j];
                float t0 = v - ps[l * 64 + p];
                float t1 = v - ps[2048 + l * 64 + p];
                d0 += t0 * t0;
                d1 += t1 * t1;
            }
            float er  = fminf(fmaxf(d0 * REDV, -CLIPV), CLIPV);
            float er1 = fminf(fmaxf(d1 * REDV, -CLIPV), CLIPV);
            // logits layout: [B, K, P]
            out[((size_t)b * Kn + k) * Pn + p] = er;
            out[(size_t)Bn * Kn * Pn + ((size_t)b * Kn + k) * Pn + p] = er1;
            ers[j]  = er;
            er1s[j] = er1;
        }
        __syncthreads();
        if (tid < 4) {
            int bb = tid & 1;
            const float* src = (tid < 2) ? ers : er1s;
            float s = 0.f;
            #pragma unroll
            for (int p = 0; p < 64; p++) s += src[bb * 64 + p];
            if (tid < 2) f_dev[k * Bn + b0 + bb]  = s;
            else         f1_dev[k * Bn + b0 + bb] = s;
        }
    }
    __syncthreads();

    // =========== Stage 5: last-CTA finalize (pull/push) ===========
    {
        __threadfence();
        __shared__ unsigned int s_is_last;
        if (tid == 0) {
            unsigned int old = atomicAdd(&done_ctr, 1u);
            s_is_last = (old == gridDim.x * gridDim.y - 1) ? 1u : 0u;
        }
        __syncthreads();
        if (s_is_last) {
            __threadfence();
            float* s_pull = misc;          // [128]
            float* s_push = misc + 128;    // [128]
            float pull = 0.f, push = 0.f;
            if (tid < Kn) {
                float se = 0.f, sc = 0.f;
                int ne = 0, nc = 0;
                #pragma unroll 8
                for (int b = 0; b < Bn; b++) {
                    float fv  = __ldcg(&f_dev[tid * Bn + b]);
                    float f1v = __ldcg(&f1_dev[tid * Bn + b]);
                    if (ycls[b] == tid) { se += f1v; ne++; }
                    else if (fv < PUSHT) { sc += fv; nc++; }
                }
                if (ne > 0) pull = se / (float)ne;
                if (nc > 0) push = sc / (float)nc;
            }
            if (tid < 128) {
                s_pull[tid] = pull;
                s_push[tid] = push;
            }
            __syncthreads();
            for (int s = 64; s > 0; s >>= 1) {
                if (tid < s) {
                    s_pull[tid] += s_pull[tid + s];
                    s_push[tid] += s_push[tid + s];
                }
                __syncthreads();
            }
            if (tid == 0) {
                size_t base = (size_t)2 * Bn * Kn * Pn;
                out[base]     = s_pull[0];
                out[base + 1] = s_push[0];
                done_ctr = 0;   // reset for next graph replay (deterministic)
            }
        }
    }
}

extern "C" void kernel_launch(void* const* d_in, const int* in_sizes, int n_in,
                              void* d_out, int out_size)
{
    const float* x    = (const float*)d_in[0];
    const int*   ycls = (const int*)  d_in[1];
    // d_in[2], d_in[3]: safe_margin_all / safe_distance_all — unused by reference
    const float* W1   = (const float*)d_in[4];
    const float* W2   = (const float*)d_in[5];
    const float* W3   = (const float*)d_in[6];
    const float* pr0  = (const float*)d_in[7];
    const float* pr1  = (const float*)d_in[8];
    float* out = (float*)d_out;

    size_t smem = SMEM_FLOATS * sizeof(float);
    cudaFuncSetAttribute(fused_cssr, cudaFuncAttributeMaxDynamicSharedMemorySize, (int)smem);

    dim3 grid(Pn * Bn / COLS, Kn);   // (32, 100)
    fused_cssr<<<grid, 256, smem>>>(x, ycls, W1, W2, W3, pr0, pr1, out);
}

// round 4
// speedup vs baseline: 3.5425x; 3.5425x over previous
#include <cuda_runtime.h>
#include <cstdint>

// ---------------- problem constants ----------------
#define Bn   64
#define Cn   512
#define Pn   64
#define Kn   100
#define H1n  64
#define HIDn 128
#define Ln   32
#define CLIPV 100.0f
#define REDV (-0.1f)
#define PUSHT 10000.0f

#define NT   128                 // j-columns per CTA
#define NJT  (Bn * Pn / NT)      // 32 j-tiles

typedef unsigned int u32;

// ---------------- device scratch ----------------
__device__ float xTg[(size_t)Bn * Pn * Cn];   // [4096][512] x transposed, tf32-rounded
__device__ float f_dev[Kn * Bn];
__device__ float f1_dev[Kn * Bn];
__device__ unsigned int done_ctr = 0;

// ---------------- smem float offsets ----------------
#define SA   68                  // stride for K<=64 operand tiles
#define SC   132                 // stride for K=128 operand tiles
#define SP   65                  // proto stride
#define OFF_XS   0               // [128][68] = 8704   (stage A, dead after)
#define OFF_W1   8704            // [64][68]  = 4352   (stage A, dead after)
#define OFF_H2   0               // [128][132]= 16896  (reuses XS/W1 region)
#define OFF_H1   16896           // [128][68] = 8704
#define OFF_W2   25600           // [128][68] = 8704
#define OFF_W3   34304           // [32][132] = 4224
#define OFF_PS0  38528           // [32][65]  = 2080
#define OFF_PS1  40608           // [32][65]  = 2080
#define OFF_ERS  42688           // [128]
#define OFF_ER1S 42816           // [128]
#define SMEM_FLOATS 42944        // 171776 bytes

// ---------------- helpers ----------------
__device__ __forceinline__ float tanh_fast(float x) {
    float y; asm("tanh.approx.f32 %0, %1;" : "=f"(y) : "f"(x)); return y;
}
__device__ __forceinline__ u32 cvt_tf32_bits(float v) {
    u32 r; asm("cvt.rna.tf32.f32 %0, %1;" : "=r"(r) : "f"(v)); return r;
}
__device__ __forceinline__ float cvt_tf32(float v) { return __uint_as_float(cvt_tf32_bits(v)); }
__device__ __forceinline__ float4 cvt4(float4 v) {
    return make_float4(cvt_tf32(v.x), cvt_tf32(v.y), cvt_tf32(v.z), cvt_tf32(v.w));
}
// D += A(16x8,row) * B(8x8,col) ; tf32 operands, f32 accum
__device__ __forceinline__ void mma_tf32(float* d, u32 a0, u32 a1, u32 a2, u32 a3, u32 b0, u32 b1) {
    asm volatile(
        "mma.sync.aligned.m16n8k8.row.col.f32.tf32.tf32.f32 "
        "{%0,%1,%2,%3}, {%4,%5,%6,%7}, {%8,%9}, {%0,%1,%2,%3};"
        : "+f"(d[0]), "+f"(d[1]), "+f"(d[2]), "+f"(d[3])
        : "r"(a0), "r"(a1), "r"(a2), "r"(a3), "r"(b0), "r"(b1));
}

// ---------------- kernel 1: global x transpose (+ tf32 rounding) ----------------
__global__ __launch_bounds__(256) void transpose_x(const float* __restrict__ x)
{
    __shared__ float t[32][65];
    const int b = blockIdx.x, cb = blockIdx.y;
    const int tid = threadIdx.x;
    #pragma unroll
    for (int pass = 0; pass < 8; pass++) {
        int idx = tid + pass * 256;
        int c = idx >> 6, p = idx & 63;
        t[c][p] = cvt_tf32(x[((size_t)b * Cn + cb * 32 + c) * Pn + p]);
    }
    __syncthreads();
    #pragma unroll
    for (int pass = 0; pass < 8; pass++) {
        int idx = tid + pass * 256;
        int p = idx >> 5, c = idx & 31;
        xTg[((size_t)b * Pn + p) * Cn + cb * 32 + c] = t[c][p];
    }
}

// ---------------- kernel 2: fused HMMA pipeline ----------------
__global__ __launch_bounds__(256, 1)
void fused_cssr_mma(const int*   __restrict__ ycls,
                    const float* __restrict__ W1,
                    const float* __restrict__ W2,
                    const float* __restrict__ W3,
                    const float* __restrict__ pr0,
                    const float* __restrict__ pr1,
                    float* __restrict__ out)
{
    extern __shared__ float sm[];
    const int k     = blockIdx.y;
    const int jtile = blockIdx.x;
    const int jbase = jtile * NT;
    const int b0    = jtile * (NT / Pn);
    const int tid   = threadIdx.x;
    const int lane  = tid & 31;
    const int warp  = tid >> 5;
    const int g     = lane >> 2;      // 0..7
    const int tig   = lane & 3;       // 0..3
    const int jw    = warp * 16;      // this warp's 16 j-rows

    // ---- resident loads: W2, W3, protos ----
    {
        const float* W2k = W2 + (size_t)k * HIDn * H1n;
        #pragma unroll
        for (int t = 0; t < 8; t++) {
            int idx = tid + t * 256;              // 2048 float4
            int o = idx >> 4, fc = idx & 15;
            float4 v = cvt4(*(const float4*)(W2k + (size_t)o * H1n + fc * 4));
            *(float4*)(sm + OFF_W2 + o * SA + fc * 4) = v;
        }
        const float* W3k = W3 + (size_t)k * Ln * HIDn;
        #pragma unroll
        for (int t = 0; t < 4; t++) {
            int idx = tid + t * 256;              // 1024 float4
            int l = idx >> 5, fc = idx & 31;
            float4 v = cvt4(*(const float4*)(W3k + (size_t)l * HIDn + fc * 4));
            *(float4*)(sm + OFF_W3 + l * SC + fc * 4) = v;
        }
        const float* p0k = pr0 + (size_t)k * Ln * Pn;
        const float* p1k = pr1 + (size_t)k * Ln * Pn;
        #pragma unroll
        for (int t = 0; t < 8; t++) {
            int idx = tid + t * 256;              // 2048 floats each
            int l = idx >> 6, p = idx & 63;
            sm[OFF_PS0 + l * SP + p] = p0k[idx];
            sm[OFF_PS1 + l * SP + p] = p1k[idx];
        }
    }

    const u32* xsu = (const u32*)(sm + OFF_XS);
    const u32* w1u = (const u32*)(sm + OFF_W1);
    const u32* h1u = (const u32*)(sm + OFF_H1);
    const u32* w2u = (const u32*)(sm + OFF_W2);
    const u32* h2u = (const u32*)(sm + OFF_H2);
    const u32* w3u = (const u32*)(sm + OFF_W3);

    // ================= Stage A: h1[j][o] = tanh( xT[j][c] * W1[o][c]^T ) =================
    float accA[8][4];
    #pragma unroll
    for (int n = 0; n < 8; n++)
        #pragma unroll
        for (int q = 0; q < 4; q++) accA[n][q] = 0.f;

    {
        const float* W1k = W1 + (size_t)k * H1n * Cn;
        for (int cc = 0; cc < 8; cc++) {
            int c0 = cc * 64;
            // xs chunk [128][64] (already tf32-rounded in xTg)
            #pragma unroll
            for (int t = 0; t < 8; t++) {
                int idx = tid + t * 256;          // 2048 float4
                int r = idx >> 4, fc = idx & 15;
                float4 v = *(const float4*)(xTg + (size_t)(jbase + r) * Cn + c0 + fc * 4);
                *(float4*)(sm + OFF_XS + r * SA + fc * 4) = v;
            }
            // w1 chunk [64][64]
            #pragma unroll
            for (int t = 0; t < 4; t++) {
                int idx = tid + t * 256;          // 1024 float4
                int o = idx >> 4, fc = idx & 15;
                float4 v = cvt4(*(const float4*)(W1k + (size_t)o * Cn + c0 + fc * 4));
                *(float4*)(sm + OFF_W1 + o * SA + fc * 4) = v;
            }
            __syncthreads();
            #pragma unroll
            for (int ks = 0; ks < 8; ks++) {
                int c = ks * 8;
                u32 a0 = xsu[(jw + g) * SA + c + tig];
                u32 a1 = xsu[(jw + g + 8) * SA + c + tig];
                u32 a2 = xsu[(jw + g) * SA + c + tig + 4];
                u32 a3 = xsu[(jw + g + 8) * SA + c + tig + 4];
                #pragma unroll
                for (int n0 = 0; n0 < 8; n0++) {
                    u32 bb0 = w1u[(n0 * 8 + g) * SA + c + tig];
                    u32 bb1 = w1u[(n0 * 8 + g) * SA + c + tig + 4];
                    mma_tf32(accA[n0], a0, a1, a2, a3, bb0, bb1);
                }
            }
            __syncthreads();
        }
    }
    // epilogue A: tanh -> tf32 -> h1 (own rows only, no sync needed)
    {
        u32* h1w = (u32*)(sm + OFF_H1);
        #pragma unroll
        for (int n0 = 0; n0 < 8; n0++) {
            uint2 v0 = make_uint2(cvt_tf32_bits(tanh_fast(accA[n0][0])),
                                  cvt_tf32_bits(tanh_fast(accA[n0][1])));
            uint2 v1 = make_uint2(cvt_tf32_bits(tanh_fast(accA[n0][2])),
                                  cvt_tf32_bits(tanh_fast(accA[n0][3])));
            *(uint2*)(h1w + (jw + g) * SA + n0 * 8 + 2 * tig)     = v0;
            *(uint2*)(h1w + (jw + g + 8) * SA + n0 * 8 + 2 * tig) = v1;
        }
    }

    // ================= Stage B: h2[j][o2] = tanh( h1[j][i] * W2[o2][i]^T ) =================
    float accB[16][4];
    #pragma unroll
    for (int n = 0; n < 16; n++)
        #pragma unroll
        for (int q = 0; q < 4; q++) accB[n][q] = 0.f;

    #pragma unroll
    for (int ks = 0; ks < 8; ks++) {              // K = 64
        int c = ks * 8;
        u32 a0 = h1u[(jw + g) * SA + c + tig];
        u32 a1 = h1u[(jw + g + 8) * SA + c + tig];
        u32 a2 = h1u[(jw + g) * SA + c + tig + 4];
        u32 a3 = h1u[(jw + g + 8) * SA + c + tig + 4];
        #pragma unroll
        for (int n0 = 0; n0 < 16; n0++) {
            u32 bb0 = w2u[(n0 * 8 + g) * SA + c + tig];
            u32 bb1 = w2u[(n0 * 8 + g) * SA + c + tig + 4];
            mma_tf32(accB[n0], a0, a1, a2, a3, bb0, bb1);
        }
    }
    // epilogue B: tanh -> tf32 -> h2 (own rows; XS/W1 region is dead)
    {
        u32* h2w = (u32*)(sm + OFF_H2);
        #pragma unroll
        for (int n0 = 0; n0 < 16; n0++) {
            uint2 v0 = make_uint2(cvt_tf32_bits(tanh_fast(accB[n0][0])),
                                  cvt_tf32_bits(tanh_fast(accB[n0][1])));
            uint2 v1 = make_uint2(cvt_tf32_bits(tanh_fast(accB[n0][2])),
                                  cvt_tf32_bits(tanh_fast(accB[n0][3])));
            *(uint2*)(h2w + (jw + g) * SC + n0 * 8 + 2 * tig)     = v0;
            *(uint2*)(h2w + (jw + g + 8) * SC + n0 * 8 + 2 * tig) = v1;
        }
    }

    // ================= Stage C: lt[j][l] = tanh( h2[j][i] * W3[l][i]^T ) =================
    float accC[4][4];
    #pragma unroll
    for (int n = 0; n < 4; n++)
        #pragma unroll
        for (int q = 0; q < 4; q++) accC[n][q] = 0.f;

    #pragma unroll
    for (int ks = 0; ks < 16; ks++) {             // K = 128
        int c = ks * 8;
        u32 a0 = h2u[(jw + g) * SC + c + tig];
        u32 a1 = h2u[(jw + g + 8) * SC + c + tig];
        u32 a2 = h2u[(jw + g) * SC + c + tig + 4];
        u32 a3 = h2u[(jw + g + 8) * SC + c + tig + 4];
        #pragma unroll
        for (int n0 = 0; n0 < 4; n0++) {
            u32 bb0 = w3u[(n0 * 8 + g) * SC + c + tig];
            u32 bb1 = w3u[(n0 * 8 + g) * SC + c + tig + 4];
            mma_tf32(accC[n0], a0, a1, a2, a3, bb0, bb1);
        }
    }

    // ---- epilogue C: tanh, distances, clip, logits, per-(k,b) sums ----
    {
        const int r0 = jw + g, r1 = jw + g + 8;
        const int p0 = (jbase + r0) & 63, p1 = (jbase + r1) & 63;
        const float* ps0 = sm + OFF_PS0;
        const float* ps1 = sm + OFF_PS1;
        float d00 = 0.f, d01 = 0.f, d10 = 0.f, d11 = 0.f;  // d<row><proto>
        #pragma unroll
        for (int n0 = 0; n0 < 4; n0++) {
            int col0 = n0 * 8 + 2 * tig, col1 = col0 + 1;
            float v00 = tanh_fast(accC[n0][0]);   // (r0,col0)
            float v01 = tanh_fast(accC[n0][1]);   // (r0,col1)
            float v10 = tanh_fast(accC[n0][2]);   // (r1,col0)
            float v11 = tanh_fast(accC[n0][3]);   // (r1,col1)
            float q;
            q = v00 - ps0[col0 * SP + p0]; d00 += q * q;
            q = v01 - ps0[col1 * SP + p0]; d00 += q * q;
            q = v00 - ps1[col0 * SP + p0]; d01 += q * q;
            q = v01 - ps1[col1 * SP + p0]; d01 += q * q;
            q = v10 - ps0[col0 * SP + p1]; d10 += q * q;
            q = v11 - ps0[col1 * SP + p1]; d10 += q * q;
            q = v10 - ps1[col0 * SP + p1]; d11 += q * q;
            q = v11 - ps1[col1 * SP + p1]; d11 += q * q;
        }
        #pragma unroll
        for (int m = 1; m <= 2; m <<= 1) {
            d00 += __shfl_xor_sync(0xFFFFFFFFu, d00, m);
            d01 += __shfl_xor_sync(0xFFFFFFFFu, d01, m);
            d10 += __shfl_xor_sync(0xFFFFFFFFu, d10, m);
            d11 += __shfl_xor_sync(0xFFFFFFFFu, d11, m);
        }
        if (tig == 0) {
            float e00 = fminf(fmaxf(d00 * REDV, -CLIPV), CLIPV);
            float e01 = fminf(fmaxf(d01 * REDV, -CLIPV), CLIPV);
            float e10 = fminf(fmaxf(d10 * REDV, -CLIPV), CLIPV);
            float e11 = fminf(fmaxf(d11 * REDV, -CLIPV), CLIPV);
            int br0 = b0 + (r0 >> 6), br1 = b0 + (r1 >> 6);
            out[((size_t)br0 * Kn + k) * Pn + p0] = e00;
            out[(size_t)Bn * Kn * Pn + ((size_t)br0 * Kn + k) * Pn + p0] = e01;
            out[((size_t)br1 * Kn + k) * Pn + p1] = e10;
            out[(size_t)Bn * Kn * Pn + ((size_t)br1 * Kn + k) * Pn + p1] = e11;
            sm[OFF_ERS + r0]  = e00;
            sm[OFF_ER1S + r0] = e01;
            sm[OFF_ERS + r1]  = e10;
            sm[OFF_ER1S + r1] = e11;
        }
    }
    __syncthreads();
    if (tid < 4) {
        int bb = tid & 1;
        const float* src = sm + ((tid < 2) ? OFF_ERS : OFF_ER1S);
        float s = 0.f;
        #pragma unroll
        for (int p = 0; p < 64; p++) s += src[bb * 64 + p];
        if (tid < 2) f_dev[k * Bn + b0 + bb]  = s;
        else         f1_dev[k * Bn + b0 + bb] = s;
    }
    __syncthreads();

    // ---- last-CTA finalize: pull/push ----
    __threadfence();
    __shared__ u32 s_is_last;
    if (tid == 0) {
        u32 old = atomicAdd(&done_ctr, 1u);
        s_is_last = (old == gridDim.x * gridDim.y - 1) ? 1u : 0u;
    }
    __syncthreads();
    if (s_is_last) {
        __threadfence();
        float* s_pull = sm;          // reuse smem
        float* s_push = sm + 128;
        float pull = 0.f, push = 0.f;
        if (tid < Kn) {
            float se = 0.f, sc = 0.f;
            int ne = 0, nc = 0;
            #pragma unroll 8
            for (int b = 0; b < Bn; b++) {
                float fv  = __ldcg(&f_dev[tid * Bn + b]);
                float f1v = __ldcg(&f1_dev[tid * Bn + b]);
                if (ycls[b] == tid) { se += f1v; ne++; }
                else if (fv < PUSHT) { sc += fv; nc++; }
            }
            if (ne > 0) pull = se / (float)ne;
            if (nc > 0) push = sc / (float)nc;
        }
        if (tid < 128) { s_pull[tid] = pull; s_push[tid] = push; }
        __syncthreads();
        for (int s = 64; s > 0; s >>= 1) {
            if (tid < s) { s_pull[tid] += s_pull[tid + s]; s_push[tid] += s_push[tid + s]; }
            __syncthreads();
        }
        if (tid == 0) {
            size_t base = (size_t)2 * Bn * Kn * Pn;
            out[base]     = s_pull[0];
            out[base + 1] = s_push[0];
            done_ctr = 0;   // deterministic across graph replays
        }
    }
}

extern "C" void kernel_launch(void* const* d_in, const int* in_sizes, int n_in,
                              void* d_out, int out_size)
{
    const float* x    = (const float*)d_in[0];
    const int*   ycls = (const int*)  d_in[1];
    const float* W1   = (const float*)d_in[4];
    const float* W2   = (const float*)d_in[5];
    const float* W3   = (const float*)d_in[6];
    const float* pr0  = (const float*)d_in[7];
    const float* pr1  = (const float*)d_in[8];
    float* out = (float*)d_out;

    transpose_x<<<dim3(Bn, Cn / 32), 256>>>(x);

    size_t smem = SMEM_FLOATS * sizeof(float);
    cudaFuncSetAttribute(fused_cssr_mma, cudaFuncAttributeMaxDynamicSharedMemorySize, (int)smem);
    fused_cssr_mma<<<dim3(NJT, Kn), 256, smem>>>(ycls, W1, W2, W3, pr0, pr1, out);
}

// round 5
// speedup vs baseline: 4.3982x; 1.2416x over previous
#include <cuda_runtime.h>
#include <cstdint>

// ---------------- problem constants ----------------
#define Bn   64
#define Cn   512
#define Pn   64
#define Kn   100
#define H1n  64
#define HIDn 128
#define Ln   32
#define CLIPV 100.0f
#define REDV (-0.1f)
#define PUSHT 10000.0f

typedef unsigned int u32;

// ---------------- device scratch (fragment-layout, tf32-rounded) ----------------
// xF : A-frags. [R 256][kb 64][lane 32] uint4 = {x(R16+g, kb8+t), x(g+8,..), x(g, t+4), x(g+8, t+4)}
__device__ uint4 xF[(size_t)256 * 64 * 32];
// w1F: B-frags paired n0. [k][kb 64][np 4][lane] uint4 = {W(o0,c),W(o0,c+4),W(o1,c),W(o1,c+4)}, o0=np*16+g, o1=o0+8, c=kb*8+t
__device__ uint4 w1F[(size_t)Kn * 64 * 4 * 32];
__device__ uint4 w2F[(size_t)Kn * 8 * 8 * 32];
__device__ uint4 w3F[(size_t)Kn * 16 * 2 * 32];
__device__ float f_dev[Kn * Bn];
__device__ float f1_dev[Kn * Bn];
__device__ unsigned int done_ctr = 0;

// ---------------- smem regions (bytes) ----------------
#define RING0   0          // 16KB W1 ring buf0 | later h1f (32KB) | later h2f lower
#define RING1   16384      // 16KB W1 ring buf1
#define W2S     32768      // 32KB W2 frags | later h2f upper
#define W3S     65536      // 16KB W3 frags
#define PSS     81920      // 2 x [32][68] floats = 17408B
#define ERSOF   99328      // ers[128], er1s[128]
#define SMEM_BYTES 100480

// ---------------- helpers ----------------
__device__ __forceinline__ u32 smem_u32(const void* p) {
    u32 a;
    asm("{ .reg .u64 t; cvta.to.shared.u64 t, %1; cvt.u32.u64 %0, t; }" : "=r"(a) : "l"(p));
    return a;
}
__device__ __forceinline__ float tanh_fast(float x) {
    float y; asm("tanh.approx.f32 %0, %1;" : "=f"(y) : "f"(x)); return y;
}
__device__ __forceinline__ u32 cvt_tf32_bits(float v) {
    u32 r; asm("cvt.rna.tf32.f32 %0, %1;" : "=r"(r) : "f"(v)); return r;
}
__device__ __forceinline__ float cvt_tf32(float v) { return __uint_as_float(cvt_tf32_bits(v)); }

__device__ __forceinline__ void mma_tf32(float* d, uint4 a, u32 b0, u32 b1) {
    asm volatile(
        "mma.sync.aligned.m16n8k8.row.col.f32.tf32.tf32.f32 "
        "{%0,%1,%2,%3}, {%4,%5,%6,%7}, {%8,%9}, {%0,%1,%2,%3};"
        : "+f"(d[0]), "+f"(d[1]), "+f"(d[2]), "+f"(d[3])
        : "r"(a.x), "r"(a.y), "r"(a.z), "r"(a.w), "r"(b0), "r"(b1));
}

#define CP16(saddr, gptr) \
    asm volatile("cp.async.cg.shared.global [%0], [%1], 16;" :: "r"(saddr), "l"(gptr) : "memory")
#define CP_COMMIT() asm volatile("cp.async.commit_group;" ::: "memory")
#define CP_WAIT(n)  asm volatile("cp.async.wait_group %0;" :: "n"(n) : "memory")

// ================= pre-kernel: permute x -> xF =================
__global__ __launch_bounds__(256) void permute_x(const float* __restrict__ x)
{
    __shared__ float t[64][65];
    const int b = blockIdx.x, cg = blockIdx.y;   // cg: group of 64 channels
    const int tid = threadIdx.x;
    #pragma unroll
    for (int i = 0; i < 4; i++) {
        int idx = tid + i * 256;                 // 0..1023 float4s
        int cc = idx >> 4, p4 = (idx & 15) * 4;
        const float* src = x + ((size_t)(b * Cn + cg * 64 + cc)) * Pn + p4;
        float4 v = *(const float4*)src;
        t[cc][p4 + 0] = cvt_tf32(v.x); t[cc][p4 + 1] = cvt_tf32(v.y);
        t[cc][p4 + 2] = cvt_tf32(v.z); t[cc][p4 + 3] = cvt_tf32(v.w);
    }
    __syncthreads();
    #pragma unroll
    for (int i = 0; i < 4; i++) {
        int o = tid + i * 256;                   // 0..1023 uint4s
        int lane = o & 31, kb = (o >> 5) & 7, Rl = o >> 8;
        int g = lane >> 2, tt = lane & 3;
        int cc = kb * 8 + tt, pA = Rl * 16 + g;
        uint4 v;
        v.x = __float_as_uint(t[cc][pA]);
        v.y = __float_as_uint(t[cc][pA + 8]);
        v.z = __float_as_uint(t[cc + 4][pA]);
        v.w = __float_as_uint(t[cc + 4][pA + 8]);
        xF[((size_t)(b * 4 + Rl) * 64 + cg * 8 + kb) * 32 + lane] = v;
    }
}

// ================= pre-kernels: permute weights =================
__global__ __launch_bounds__(256) void permute_w1(const float* __restrict__ W1)
{
    int id = blockIdx.x * 256 + threadIdx.x;     // 819200
    int lane = id & 31, np = (id >> 5) & 3, kb = (id >> 7) & 63, k = id >> 13;
    int g = lane >> 2, tt = lane & 3;
    int o0 = np * 16 + g, o1 = o0 + 8, c = kb * 8 + tt;
    const float* W = W1 + (size_t)k * H1n * Cn;
    uint4 v;
    v.x = cvt_tf32_bits(W[(size_t)o0 * Cn + c]);
    v.y = cvt_tf32_bits(W[(size_t)o0 * Cn + c + 4]);
    v.z = cvt_tf32_bits(W[(size_t)o1 * Cn + c]);
    v.w = cvt_tf32_bits(W[(size_t)o1 * Cn + c + 4]);
    w1F[id] = v;
}
__global__ __launch_bounds__(256) void permute_w2(const float* __restrict__ W2)
{
    int id = blockIdx.x * 256 + threadIdx.x;     // 204800
    int lane = id & 31, np = (id >> 5) & 7, kb = (id >> 8) & 7, k = id >> 11;
    int g = lane >> 2, tt = lane & 3;
    int o0 = np * 16 + g, o1 = o0 + 8, c = kb * 8 + tt;
    const float* W = W2 + (size_t)k * HIDn * H1n;
    uint4 v;
    v.x = cvt_tf32_bits(W[(size_t)o0 * H1n + c]);
    v.y = cvt_tf32_bits(W[(size_t)o0 * H1n + c + 4]);
    v.z = cvt_tf32_bits(W[(size_t)o1 * H1n + c]);
    v.w = cvt_tf32_bits(W[(size_t)o1 * H1n + c + 4]);
    w2F[id] = v;
}
__global__ __launch_bounds__(256) void permute_w3(const float* __restrict__ W3)
{
    int id = blockIdx.x * 256 + threadIdx.x;     // 102400
    int lane = id & 31, np = (id >> 5) & 1, kb = (id >> 6) & 15, k = id >> 10;
    int g = lane >> 2, tt = lane & 3;
    int o0 = np * 16 + g, o1 = o0 + 8, c = kb * 8 + tt;
    const float* W = W3 + (size_t)k * Ln * HIDn;
    uint4 v;
    v.x = cvt_tf32_bits(W[(size_t)o0 * HIDn + c]);
    v.y = cvt_tf32_bits(W[(size_t)o0 * HIDn + c + 4]);
    v.z = cvt_tf32_bits(W[(size_t)o1 * HIDn + c]);
    v.w = cvt_tf32_bits(W[(size_t)o1 * HIDn + c + 4]);
    w3F[id] = v;
}

// ================= main fused kernel: 128 threads, 4 warps, M=32/warp =================
__global__ __launch_bounds__(128, 2)
void fused_main(const int* __restrict__ ycls, const float* __restrict__ pr0,
                const float* __restrict__ pr1, float* __restrict__ out)
{
    extern __shared__ char smb[];
    const u32 smu = smem_u32(smb);
    const int k     = blockIdx.y;
    const int jtile = blockIdx.x;
    const int jbase = jtile * 128;
    const int b0    = jtile * 2;
    const int tid   = threadIdx.x;
    const int lane  = tid & 31;
    const int warp  = tid >> 5;
    const int g     = lane >> 2;
    const int tt    = lane & 3;
    const int sw    = 4 * g;                     // swizzle term (col ^ 4g)

    // ---- PS fill (plain, padded stride 68) ----
    {
        const float* p0k = pr0 + (size_t)k * Ln * Pn;
        const float* p1k = pr1 + (size_t)k * Ln * Pn;
        #pragma unroll
        for (int i = 0; i < 4; i++) {
            int idx = tid + i * 128;             // 0..511 float4
            int l = idx >> 4, p4 = (idx & 15) * 4;
            *(float4*)(smb + PSS + (l * 68 + p4) * 4)          = *(const float4*)(p0k + idx * 4);
            *(float4*)(smb + PSS + (2176 + l * 68 + p4) * 4)   = *(const float4*)(p1k + idx * 4);
        }
    }
    // ---- cp.async: W2 (2048 u4) + W3 (1024 u4) as one group; then W1 chunk 0 ----
    {
        const uint4* w2k = w2F + (size_t)k * 2048;
        const uint4* w3k = w3F + (size_t)k * 1024;
        #pragma unroll
        for (int i = 0; i < 16; i++) CP16(smu + W2S + (tid + i * 128) * 16, w2k + tid + i * 128);
        #pragma unroll
        for (int i = 0; i < 8;  i++) CP16(smu + W3S + (tid + i * 128) * 16, w3k + tid + i * 128);
        CP_COMMIT();
    }
    const uint4* w1k = w1F + (size_t)k * 8192;
    {
        #pragma unroll
        for (int i = 0; i < 8; i++) CP16(smu + RING0 + (tid + i * 128) * 16, w1k + tid + i * 128);
        CP_COMMIT();
    }

    // ================= Stage A: M=32/warp, N=64, K=512 =================
    const int R0 = jtile * 8 + warp * 2, R1 = R0 + 1;
    float accA[8][2][4];
    #pragma unroll
    for (int n = 0; n < 8; n++)
        #pragma unroll
        for (int r = 0; r < 2; r++)
            #pragma unroll
            for (int q = 0; q < 4; q++) accA[n][r][q] = 0.f;

    uint4 aA = xF[((size_t)R0 * 64 + 0) * 32 + lane];
    uint4 aB = xF[((size_t)R1 * 64 + 0) * 32 + lane];

    for (int cc = 0; cc < 8; cc++) {
        __syncthreads();                         // ring buf (cc+1)&1 free
        if (cc < 7) {
            u32 dst = smu + ((cc + 1) & 1) * 16384;
            const uint4* src = w1k + (cc + 1) * 1024;
            #pragma unroll
            for (int i = 0; i < 8; i++) CP16(dst + (tid + i * 128) * 16, src + tid + i * 128);
            CP_COMMIT();
            CP_WAIT(1);
        } else {
            CP_WAIT(0);
        }
        __syncthreads();
        const char* rb = smb + (cc & 1) * 16384;
        #pragma unroll
        for (int ks = 0; ks < 8; ks++) {
            int kb = cc * 8 + ks;
            uint4 nA = aA, nB = aB;
            if (kb < 63) {
                nA = xF[((size_t)R0 * 64 + kb + 1) * 32 + lane];
                nB = xF[((size_t)R1 * 64 + kb + 1) * 32 + lane];
            }
            #pragma unroll
            for (int np = 0; np < 4; np++) {
                uint4 bv = *(const uint4*)(rb + ((ks * 4 + np) * 32 + lane) * 16);
                mma_tf32(accA[2 * np][0],     aA, bv.x, bv.y);
                mma_tf32(accA[2 * np][1],     aB, bv.x, bv.y);
                mma_tf32(accA[2 * np + 1][0], aA, bv.z, bv.w);
                mma_tf32(accA[2 * np + 1][1], aB, bv.z, bv.w);
            }
            aA = nA; aB = nB;
        }
    }

    // ---- epilogue A: tanh -> tf32 -> h1f (warp-private, [32][64] swizzled) ----
    __syncthreads();                             // ring fully dead
    {
        char* h1 = smb + warp * 8192;
        #pragma unroll
        for (int n0 = 0; n0 < 8; n0++) {
            int c0s = (n0 * 8 + 2 * tt) ^ sw;
            #pragma unroll
            for (int rt = 0; rt < 2; rt++) {
                int row = rt * 16 + g;
                uint2 v0 = make_uint2(cvt_tf32_bits(tanh_fast(accA[n0][rt][0])),
                                      cvt_tf32_bits(tanh_fast(accA[n0][rt][1])));
                uint2 v1 = make_uint2(cvt_tf32_bits(tanh_fast(accA[n0][rt][2])),
                                      cvt_tf32_bits(tanh_fast(accA[n0][rt][3])));
                *(uint2*)(h1 + (row * 64 + c0s) * 4)       = v0;
                *(uint2*)(h1 + ((row + 8) * 64 + c0s) * 4) = v1;
            }
        }
    }
    __syncwarp();

    // ================= Stage B: M=32, N=128, K=64 =================
    float accB[16][2][4];
    #pragma unroll
    for (int n = 0; n < 16; n++)
        #pragma unroll
        for (int r = 0; r < 2; r++)
            #pragma unroll
            for (int q = 0; q < 4; q++) accB[n][r][q] = 0.f;
    {
        const char* h1 = smb + warp * 8192;
        #pragma unroll
        for (int ks = 0; ks < 8; ks++) {
            int c0 = (ks * 8 + tt) ^ sw, c1 = (ks * 8 + tt + 4) ^ sw;
            uint4 afr[2];
            #pragma unroll
            for (int rt = 0; rt < 2; rt++) {
                int row = rt * 16 + g;
                afr[rt].x = *(const u32*)(h1 + (row * 64 + c0) * 4);
                afr[rt].y = *(const u32*)(h1 + ((row + 8) * 64 + c0) * 4);
                afr[rt].z = *(const u32*)(h1 + (row * 64 + c1) * 4);
                afr[rt].w = *(const u32*)(h1 + ((row + 8) * 64 + c1) * 4);
            }
            #pragma unroll
            for (int np = 0; np < 8; np++) {
                uint4 bv = *(const uint4*)(smb + W2S + ((ks * 8 + np) * 32 + lane) * 16);
                mma_tf32(accB[2 * np][0],     afr[0], bv.x, bv.y);
                mma_tf32(accB[2 * np][1],     afr[1], bv.x, bv.y);
                mma_tf32(accB[2 * np + 1][0], afr[0], bv.z, bv.w);
                mma_tf32(accB[2 * np + 1][1], afr[1], bv.z, bv.w);
            }
        }
    }

    // ---- epilogue B: tanh -> tf32 -> h2f (warp-private [32][128] swizzled; overlays ring+W2) ----
    __syncthreads();                             // all warps done reading W2
    {
        char* h2 = smb + warp * 16384;
        #pragma unroll
        for (int n0 = 0; n0 < 16; n0++) {
            int c0s = (n0 * 8 + 2 * tt) ^ sw;
            #pragma unroll
            for (int rt = 0; rt < 2; rt++) {
                int row = rt * 16 + g;
                uint2 v0 = make_uint2(cvt_tf32_bits(tanh_fast(accB[n0][rt][0])),
                                      cvt_tf32_bits(tanh_fast(accB[n0][rt][1])));
                uint2 v1 = make_uint2(cvt_tf32_bits(tanh_fast(accB[n0][rt][2])),
                                      cvt_tf32_bits(tanh_fast(accB[n0][rt][3])));
                *(uint2*)(h2 + (row * 128 + c0s) * 4)       = v0;
                *(uint2*)(h2 + ((row + 8) * 128 + c0s) * 4) = v1;
            }
        }
    }
    __syncwarp();

    // ================= Stage C: M=32, N=32, K=128 =================
    float accC[4][2][4];
    #pragma unroll
    for (int n = 0; n < 4; n++)
        #pragma unroll
        for (int r = 0; r < 2; r++)
            #pragma unroll
            for (int q = 0; q < 4; q++) accC[n][r][q] = 0.f;
    {
        const char* h2 = smb + warp * 16384;
        #pragma unroll
        for (int ks = 0; ks < 16; ks++) {
            int c0 = (ks * 8 + tt) ^ sw, c1 = (ks * 8 + tt + 4) ^ sw;
            uint4 afr[2];
            #pragma unroll
            for (int rt = 0; rt < 2; rt++) {
                int row = rt * 16 + g;
                afr[rt].x = *(const u32*)(h2 + (row * 128 + c0) * 4);
                afr[rt].y = *(const u32*)(h2 + ((row + 8) * 128 + c0) * 4);
                afr[rt].z = *(const u32*)(h2 + (row * 128 + c1) * 4);
                afr[rt].w = *(const u32*)(h2 + ((row + 8) * 128 + c1) * 4);
            }
            #pragma unroll
            for (int np = 0; np < 2; np++) {
                uint4 bv = *(const uint4*)(smb + W3S + ((ks * 2 + np) * 32 + lane) * 16);
                mma_tf32(accC[2 * np][0],     afr[0], bv.x, bv.y);
                mma_tf32(accC[2 * np][1],     afr[1], bv.x, bv.y);
                mma_tf32(accC[2 * np + 1][0], afr[0], bv.z, bv.w);
                mma_tf32(accC[2 * np + 1][1], afr[1], bv.z, bv.w);
            }
        }
    }

    // ---- epilogue C: tanh, distances, clip, logits, per-(k,b) sums ----
    {
        const float* ps0 = (const float*)(smb + PSS);
        const float* ps1 = ps0 + 2176;
        float* ers  = (float*)(smb + ERSOF);
        float* er1s = ers + 128;
        #pragma unroll
        for (int rt = 0; rt < 2; rt++) {
            #pragma unroll
            for (int half = 0; half < 2; half++) {
                int lr = warp * 32 + rt * 16 + g + half * 8;
                int p  = (jbase + lr) & 63;
                float d0 = 0.f, d1 = 0.f;
                #pragma unroll
                for (int n0 = 0; n0 < 4; n0++) {
                    int c0 = n0 * 8 + 2 * tt, c1 = c0 + 1;
                    float v0 = tanh_fast(accC[n0][rt][half * 2 + 0]);
                    float v1 = tanh_fast(accC[n0][rt][half * 2 + 1]);
                    float q;
                    q = v0 - ps0[c0 * 68 + p]; d0 += q * q;
                    q = v1 - ps0[c1 * 68 + p]; d0 += q * q;
                    q = v0 - ps1[c0 * 68 + p]; d1 += q * q;
                    q = v1 - ps1[c1 * 68 + p]; d1 += q * q;
                }
                d0 += __shfl_xor_sync(0xFFFFFFFFu, d0, 1);
                d0 += __shfl_xor_sync(0xFFFFFFFFu, d0, 2);
                d1 += __shfl_xor_sync(0xFFFFFFFFu, d1, 1);
                d1 += __shfl_xor_sync(0xFFFFFFFFu, d1, 2);
                if (tt == 0) {
                    float er  = fminf(fmaxf(d0 * REDV, -CLIPV), CLIPV);
                    float er1 = fminf(fmaxf(d1 * REDV, -CLIPV), CLIPV);
                    int b = b0 + (lr >> 6);
                    out[((size_t)b * Kn + k) * Pn + p] = er;
                    out[(size_t)Bn * Kn * Pn + ((size_t)b * Kn + k) * Pn + p] = er1;
                    ers[lr]  = er;
                    er1s[lr] = er1;
                }
            }
        }
    }
    __syncthreads();
    if (tid < 4) {
        int bb = tid & 1;
        const float* src = (float*)(smb + ERSOF) + ((tid < 2) ? 0 : 128);
        float s = 0.f;
        #pragma unroll
        for (int p = 0; p < 64; p++) s += src[bb * 64 + p];
        if (tid < 2) f_dev[k * Bn + b0 + bb]  = s;
        else         f1_dev[k * Bn + b0 + bb] = s;
    }
    __syncthreads();

    // ---- last-CTA finalize: pull/push ----
    __threadfence();
    __shared__ u32 s_is_last;
    if (tid == 0) {
        u32 old = atomicAdd(&done_ctr, 1u);
        s_is_last = (old == gridDim.x * gridDim.y - 1) ? 1u : 0u;
    }
    __syncthreads();
    if (s_is_last) {
        __threadfence();
        float* s_pull = (float*)smb;
        float* s_push = s_pull + 128;
        float pull = 0.f, push = 0.f;
        if (tid < Kn) {
            float se = 0.f, sc = 0.f;
            int ne = 0, nc = 0;
            #pragma unroll 8
            for (int b = 0; b < Bn; b++) {
                float fv  = __ldcg(&f_dev[tid * Bn + b]);
                float f1v = __ldcg(&f1_dev[tid * Bn + b]);
                if (ycls[b] == tid) { se += f1v; ne++; }
                else if (fv < PUSHT) { sc += fv; nc++; }
            }
            if (ne > 0) pull = se / (float)ne;
            if (nc > 0) push = sc / (float)nc;
        }
        s_pull[tid] = pull;
        s_push[tid] = push;
        __syncthreads();
        for (int s = 64; s > 0; s >>= 1) {
            if (tid < s) { s_pull[tid] += s_pull[tid + s]; s_push[tid] += s_push[tid + s]; }
            __syncthreads();
        }
        if (tid == 0) {
            size_t base = (size_t)2 * Bn * Kn * Pn;
            out[base]     = s_pull[0];
            out[base + 1] = s_push[0];
            done_ctr = 0;   // deterministic across graph replays
        }
    }
}

extern "C" void kernel_launch(void* const* d_in, const int* in_sizes, int n_in,
                              void* d_out, int out_size)
{
    const float* x    = (const float*)d_in[0];
    const int*   ycls = (const int*)  d_in[1];
    const float* W1   = (const float*)d_in[4];
    const float* W2   = (const float*)d_in[5];
    const float* W3   = (const float*)d_in[6];
    const float* pr0  = (const float*)d_in[7];
    const float* pr1  = (const float*)d_in[8];
    float* out = (float*)d_out;

    permute_x<<<dim3(Bn, Cn / 64), 256>>>(x);
    permute_w1<<<3200, 256>>>(W1);
    permute_w2<<<800, 256>>>(W2);
    permute_w3<<<400, 256>>>(W3);

    cudaFuncSetAttribute(fused_main, cudaFuncAttributeMaxDynamicSharedMemorySize, SMEM_BYTES);
    fused_main<<<dim3(32, Kn), 128, SMEM_BYTES>>>(ycls, pr0, pr1, out);
}

// round 6
// speedup vs baseline: 7.8973x; 1.7956x over previous
#include <cuda_runtime.h>
#include <cstdint>

// ---------------- problem constants ----------------
#define Bn   64
#define Cn   512
#define Pn   64
#define Kn   100
#define H1n  64
#define HIDn 128
#define Ln   32
#define CLIPV 100.0f
#define REDV (-0.1f)
#define PUSHT 10000.0f

typedef unsigned int u32;

// ---------------- device scratch (bf16 fragment layouts) ----------------
// xF : A-frags m16n8k16. [R 256][kb 32][lane 32] uint4
__device__ uint4 xF[(size_t)256 * 32 * 32];
// wF : B-frags paired n0. uint4 = {b0(o0), b1(o0), b0(o1), b1(o1)}
__device__ uint4 w1F[(size_t)Kn * 32 * 4 * 32];
__device__ uint4 w2F[(size_t)Kn * 4 * 8 * 32];
__device__ uint4 w3F[(size_t)Kn * 8 * 2 * 32];
__device__ float f_dev[Kn * Bn];
__device__ float f1_dev[Kn * Bn];
__device__ unsigned int done_ctr = 0;

// ---------------- smem regions (bytes) ----------------
#define RING0   0          // 16KB W1 ring buf0 (later h1: 4x4KB, then h2 lower)
#define RING1   16384      // 16KB W1 ring buf1 (later h2 upper)
#define W2S     32768      // 16KB
#define W3S     49152      // 8KB
#define PSS     57344      // 2 x [32][68] floats = 17408B
#define ERSOF   74752      // 256 floats
#define SMEM_BYTES 75776

// ---------------- helpers ----------------
__device__ __forceinline__ u32 smem_u32(const void* p) {
    u32 a;
    asm("{ .reg .u64 t; cvta.to.shared.u64 t, %1; cvt.u32.u64 %0, t; }" : "=r"(a) : "l"(p));
    return a;
}
__device__ __forceinline__ float tanh_fast(float x) {
    float y; asm("tanh.approx.f32 %0, %1;" : "=f"(y) : "f"(x)); return y;
}
// pack two floats to bf16x2: lo -> bits[15:0], hi -> bits[31:16]
__device__ __forceinline__ u32 pk(float lo, float hi) {
    u32 r; asm("cvt.rn.bf16x2.f32 %0, %1, %2;" : "=r"(r) : "f"(hi), "f"(lo)); return r;
}
__device__ __forceinline__ void mma_bf16(float* d, uint4 a, u32 b0, u32 b1) {
    asm volatile(
        "mma.sync.aligned.m16n8k16.row.col.f32.bf16.bf16.f32 "
        "{%0,%1,%2,%3}, {%4,%5,%6,%7}, {%8,%9}, {%0,%1,%2,%3};"
        : "+f"(d[0]), "+f"(d[1]), "+f"(d[2]), "+f"(d[3])
        : "r"(a.x), "r"(a.y), "r"(a.z), "r"(a.w), "r"(b0), "r"(b1));
}
#define CP16(saddr, gptr) \
    asm volatile("cp.async.cg.shared.global [%0], [%1], 16;" :: "r"(saddr), "l"(gptr) : "memory")
#define CP_COMMIT() asm volatile("cp.async.commit_group;" ::: "memory")
#define CP_WAIT(n)  asm volatile("cp.async.wait_group %0;" :: "n"(n) : "memory")

// ================= pre-kernel: permute x -> xF (bf16 A-frags) =================
__global__ __launch_bounds__(256) void permute_x(const float* __restrict__ x)
{
    __shared__ float t[64][65];
    const int b = blockIdx.x, cg = blockIdx.y;   // cg: group of 64 channels
    const int tid = threadIdx.x;
    #pragma unroll
    for (int i = 0; i < 4; i++) {
        int idx = tid + i * 256;                 // 0..1023 float4s
        int cc = idx >> 4, p4 = (idx & 15) * 4;
        float4 v = *(const float4*)(x + ((size_t)(b * Cn + cg * 64 + cc)) * Pn + p4);
        t[cc][p4 + 0] = v.x; t[cc][p4 + 1] = v.y; t[cc][p4 + 2] = v.z; t[cc][p4 + 3] = v.w;
    }
    __syncthreads();
    #pragma unroll
    for (int i = 0; i < 2; i++) {
        int o = tid + i * 256;                   // 0..511 uint4s
        int lane = o & 31, kbl = (o >> 5) & 3, Rl = (o >> 7) & 3;
        int g = lane >> 2, tt = lane & 3;
        int c0 = kbl * 16 + 2 * tt, pA = Rl * 16 + g;
        uint4 v;
        v.x = pk(t[c0][pA],       t[c0 + 1][pA]);
        v.y = pk(t[c0][pA + 8],   t[c0 + 1][pA + 8]);
        v.z = pk(t[c0 + 8][pA],   t[c0 + 9][pA]);
        v.w = pk(t[c0 + 8][pA + 8], t[c0 + 9][pA + 8]);
        xF[((size_t)(b * 4 + Rl) * 32 + cg * 4 + kbl) * 32 + lane] = v;
    }
}

// ================= pre-kernels: permute weights (bf16 B-frags) =================
__global__ __launch_bounds__(256) void permute_w1(const float* __restrict__ W1)
{
    int id = blockIdx.x * 256 + threadIdx.x;     // 409600
    int lane = id & 31, np = (id >> 5) & 3, kb = (id >> 7) & 31, k = id >> 12;
    int g = lane >> 2, tt = lane & 3;
    int o0 = np * 16 + g, o1 = o0 + 8, c = kb * 16 + 2 * tt;
    const float* W = W1 + (size_t)k * H1n * Cn;
    uint4 v;
    v.x = pk(W[(size_t)o0 * Cn + c],     W[(size_t)o0 * Cn + c + 1]);
    v.y = pk(W[(size_t)o0 * Cn + c + 8], W[(size_t)o0 * Cn + c + 9]);
    v.z = pk(W[(size_t)o1 * Cn + c],     W[(size_t)o1 * Cn + c + 1]);
    v.w = pk(W[(size_t)o1 * Cn + c + 8], W[(size_t)o1 * Cn + c + 9]);
    w1F[id] = v;
}
__global__ __launch_bounds__(256) void permute_w2(const float* __restrict__ W2)
{
    int id = blockIdx.x * 256 + threadIdx.x;     // 102400
    int lane = id & 31, np = (id >> 5) & 7, kb = (id >> 8) & 3, k = id >> 10;
    int g = lane >> 2, tt = lane & 3;
    int o0 = np * 16 + g, o1 = o0 + 8, c = kb * 16 + 2 * tt;
    const float* W = W2 + (size_t)k * HIDn * H1n;
    uint4 v;
    v.x = pk(W[(size_t)o0 * H1n + c],     W[(size_t)o0 * H1n + c + 1]);
    v.y = pk(W[(size_t)o0 * H1n + c + 8], W[(size_t)o0 * H1n + c + 9]);
    v.z = pk(W[(size_t)o1 * H1n + c],     W[(size_t)o1 * H1n + c + 1]);
    v.w = pk(W[(size_t)o1 * H1n + c + 8], W[(size_t)o1 * H1n + c + 9]);
    w2F[id] = v;
}
__global__ __launch_bounds__(256) void permute_w3(const float* __restrict__ W3)
{
    int id = blockIdx.x * 256 + threadIdx.x;     // 51200
    int lane = id & 31, np = (id >> 5) & 1, kb = (id >> 6) & 7, k = id >> 9;
    int g = lane >> 2, tt = lane & 3;
    int o0 = np * 16 + g, o1 = o0 + 8, c = kb * 16 + 2 * tt;
    const float* W = W3 + (size_t)k * Ln * HIDn;
    uint4 v;
    v.x = pk(W[(size_t)o0 * HIDn + c],     W[(size_t)o0 * HIDn + c + 1]);
    v.y = pk(W[(size_t)o0 * HIDn + c + 8], W[(size_t)o0 * HIDn + c + 9]);
    v.z = pk(W[(size_t)o1 * HIDn + c],     W[(size_t)o1 * HIDn + c + 1]);
    v.w = pk(W[(size_t)o1 * HIDn + c + 8], W[(size_t)o1 * HIDn + c + 9]);
    w3F[id] = v;
}

// ================= main fused kernel: 128 threads, 4 warps, M=32/warp =================
__global__ __launch_bounds__(128, 2)
void fused_main(const int* __restrict__ ycls, const float* __restrict__ pr0,
                const float* __restrict__ pr1, float* __restrict__ out)
{
    extern __shared__ char smb[];
    const u32 smu = smem_u32(smb);
    const int k     = blockIdx.y;
    const int jtile = blockIdx.x;
    const int jbase = jtile * 128;
    const int b0    = jtile * 2;
    const int tid   = threadIdx.x;
    const int lane  = tid & 31;
    const int warp  = tid >> 5;
    const int g     = lane >> 2;
    const int tt    = lane & 3;

    // ---- PS fill (padded stride 68) ----
    {
        const float* p0k = pr0 + (size_t)k * Ln * Pn;
        const float* p1k = pr1 + (size_t)k * Ln * Pn;
        #pragma unroll
        for (int i = 0; i < 4; i++) {
            int idx = tid + i * 128;             // 0..511 float4
            int l = idx >> 4, p4 = (idx & 15) * 4;
            *(float4*)(smb + PSS + (l * 68 + p4) * 4)        = *(const float4*)(p0k + idx * 4);
            *(float4*)(smb + PSS + (2176 + l * 68 + p4) * 4) = *(const float4*)(p1k + idx * 4);
        }
    }
    // ---- cp.async: W2 (1024 u4) + W3 (512 u4); then W1 chunk 0 ----
    {
        const uint4* w2k = w2F + (size_t)k * 1024;
        const uint4* w3k = w3F + (size_t)k * 512;
        #pragma unroll
        for (int i = 0; i < 8; i++) CP16(smu + W2S + (tid + i * 128) * 16, w2k + tid + i * 128);
        #pragma unroll
        for (int i = 0; i < 4; i++) CP16(smu + W3S + (tid + i * 128) * 16, w3k + tid + i * 128);
        CP_COMMIT();
    }
    const uint4* w1k = w1F + (size_t)k * 4096;
    {
        #pragma unroll
        for (int i = 0; i < 8; i++) CP16(smu + RING0 + (tid + i * 128) * 16, w1k + tid + i * 128);
        CP_COMMIT();
    }

    // ================= Stage A: M=32/warp, N=64, K=512 (32 kb16-steps) =================
    const int R0 = jtile * 8 + warp * 2, R1 = R0 + 1;
    float accA[8][2][4];
    #pragma unroll
    for (int n = 0; n < 8; n++)
        #pragma unroll
        for (int r = 0; r < 2; r++)
            #pragma unroll
            for (int q = 0; q < 4; q++) accA[n][r][q] = 0.f;

    uint4 aA = xF[((size_t)R0 * 32 + 0) * 32 + lane];
    uint4 aB = xF[((size_t)R1 * 32 + 0) * 32 + lane];

    for (int cc = 0; cc < 4; cc++) {
        __syncthreads();
        if (cc < 3) {
            u32 dst = smu + ((cc + 1) & 1) * 16384;
            const uint4* src = w1k + (cc + 1) * 1024;
            #pragma unroll
            for (int i = 0; i < 8; i++) CP16(dst + (tid + i * 128) * 16, src + tid + i * 128);
            CP_COMMIT();
            CP_WAIT(1);
        } else {
            CP_WAIT(0);
        }
        __syncthreads();
        const char* rb = smb + (cc & 1) * 16384;
        #pragma unroll
        for (int ks = 0; ks < 8; ks++) {
            int kb = cc * 8 + ks;
            uint4 nA = aA, nB = aB;
            if (kb < 31) {
                nA = xF[((size_t)R0 * 32 + kb + 1) * 32 + lane];
                nB = xF[((size_t)R1 * 32 + kb + 1) * 32 + lane];
            }
            #pragma unroll
            for (int np = 0; np < 4; np++) {
                uint4 bv = *(const uint4*)(rb + ((ks * 4 + np) * 32 + lane) * 16);
                mma_bf16(accA[2 * np][0],     aA, bv.x, bv.y);
                mma_bf16(accA[2 * np][1],     aB, bv.x, bv.y);
                mma_bf16(accA[2 * np + 1][0], aA, bv.z, bv.w);
                mma_bf16(accA[2 * np + 1][1], aB, bv.z, bv.w);
            }
            aA = nA; aB = nB;
        }
    }

    // ---- epilogue A: tanh -> bf16x2 -> h1 (warp-private [32 rows][32 words], rotated) ----
    {
        u32* h1 = (u32*)(smb + warp * 4096);
        #pragma unroll
        for (int n0 = 0; n0 < 8; n0++) {
            int cA = (n0 * 4 + tt + 4 * g) & 31;
            #pragma unroll
            for (int rt = 0; rt < 2; rt++) {
                int row = rt * 16 + g;
                h1[row * 32 + cA]       = pk(tanh_fast(accA[n0][rt][0]), tanh_fast(accA[n0][rt][1]));
                h1[(row + 8) * 32 + cA] = pk(tanh_fast(accA[n0][rt][2]), tanh_fast(accA[n0][rt][3]));
            }
        }
    }
    __syncwarp();

    // ================= Stage B: M=32, N=128, K=64 (4 kb16-steps) =================
    float accB[16][2][4];
    #pragma unroll
    for (int n = 0; n < 16; n++)
        #pragma unroll
        for (int r = 0; r < 2; r++)
            #pragma unroll
            for (int q = 0; q < 4; q++) accB[n][r][q] = 0.f;
    {
        const u32* h1 = (const u32*)(smb + warp * 4096);
        #pragma unroll
        for (int kb = 0; kb < 4; kb++) {
            int cx = (kb * 8 + tt + 4 * g) & 31;
            int cz = (kb * 8 + tt + 4 + 4 * g) & 31;
            uint4 af[2];
            #pragma unroll
            for (int rt = 0; rt < 2; rt++) {
                int row = rt * 16 + g;
                af[rt].x = h1[row * 32 + cx];
                af[rt].y = h1[(row + 8) * 32 + cx];
                af[rt].z = h1[row * 32 + cz];
                af[rt].w = h1[(row + 8) * 32 + cz];
            }
            #pragma unroll
            for (int np = 0; np < 8; np++) {
                uint4 bv = *(const uint4*)(smb + W2S + ((kb * 8 + np) * 32 + lane) * 16);
                mma_bf16(accB[2 * np][0],     af[0], bv.x, bv.y);
                mma_bf16(accB[2 * np][1],     af[1], bv.x, bv.y);
                mma_bf16(accB[2 * np + 1][0], af[0], bv.z, bv.w);
                mma_bf16(accB[2 * np + 1][1], af[1], bv.z, bv.w);
            }
        }
    }
    __syncthreads();                             // h2 overlays ring + all h1

    // ---- epilogue B: tanh -> bf16x2 -> h2 (warp-private [32 rows][64 words], rotated) ----
    {
        u32* h2 = (u32*)(smb + warp * 8192);
        #pragma unroll
        for (int n0 = 0; n0 < 16; n0++) {
            int cB = (n0 * 4 + tt + 4 * g) & 63;
            #pragma unroll
            for (int rt = 0; rt < 2; rt++) {
                int row = rt * 16 + g;
                h2[row * 64 + cB]       = pk(tanh_fast(accB[n0][rt][0]), tanh_fast(accB[n0][rt][1]));
                h2[(row + 8) * 64 + cB] = pk(tanh_fast(accB[n0][rt][2]), tanh_fast(accB[n0][rt][3]));
            }
        }
    }
    __syncwarp();

    // ================= Stage C: M=32, N=32, K=128 (8 kb16-steps) =================
    float accC[4][2][4];
    #pragma unroll
    for (int n = 0; n < 4; n++)
        #pragma unroll
        for (int r = 0; r < 2; r++)
            #pragma unroll
            for (int q = 0; q < 4; q++) accC[n][r][q] = 0.f;
    {
        const u32* h2 = (const u32*)(smb + warp * 8192);
        #pragma unroll
        for (int kb = 0; kb < 8; kb++) {
            int cx = (kb * 8 + tt + 4 * g) & 63;
            int cz = (kb * 8 + tt + 4 + 4 * g) & 63;
            uint4 af[2];
            #pragma unroll
            for (int rt = 0; rt < 2; rt++) {
                int row = rt * 16 + g;
                af[rt].x = h2[row * 64 + cx];
                af[rt].y = h2[(row + 8) * 64 + cx];
                af[rt].z = h2[row * 64 + cz];
                af[rt].w = h2[(row + 8) * 64 + cz];
            }
            #pragma unroll
            for (int np = 0; np < 2; np++) {
                uint4 bv = *(const uint4*)(smb + W3S + ((kb * 2 + np) * 32 + lane) * 16);
                mma_bf16(accC[2 * np][0],     af[0], bv.x, bv.y);
                mma_bf16(accC[2 * np][1],     af[1], bv.x, bv.y);
                mma_bf16(accC[2 * np + 1][0], af[0], bv.z, bv.w);
                mma_bf16(accC[2 * np + 1][1], af[1], bv.z, bv.w);
            }
        }
    }

    // ---- epilogue C: tanh, distances, clip, logits, per-(k,b) sums ----
    {
        const float* ps0 = (const float*)(smb + PSS);
        const float* ps1 = ps0 + 2176;
        float* ers  = (float*)(smb + ERSOF);
        float* er1s = ers + 128;
        #pragma unroll
        for (int rt = 0; rt < 2; rt++) {
            #pragma unroll
            for (int half = 0; half < 2; half++) {
                int lr = warp * 32 + rt * 16 + g + half * 8;
                int p  = (jbase + lr) & 63;
                float d0 = 0.f, d1 = 0.f;
                #pragma unroll
                for (int n0 = 0; n0 < 4; n0++) {
                    int c0 = n0 * 8 + 2 * tt, c1 = c0 + 1;
                    float v0 = tanh_fast(accC[n0][rt][half * 2 + 0]);
                    float v1 = tanh_fast(accC[n0][rt][half * 2 + 1]);
                    float q;
                    q = v0 - ps0[c0 * 68 + p]; d0 += q * q;
                    q = v1 - ps0[c1 * 68 + p]; d0 += q * q;
                    q = v0 - ps1[c0 * 68 + p]; d1 += q * q;
                    q = v1 - ps1[c1 * 68 + p]; d1 += q * q;
                }
                d0 += __shfl_xor_sync(0xFFFFFFFFu, d0, 1);
                d0 += __shfl_xor_sync(0xFFFFFFFFu, d0, 2);
                d1 += __shfl_xor_sync(0xFFFFFFFFu, d1, 1);
                d1 += __shfl_xor_sync(0xFFFFFFFFu, d1, 2);
                if (tt == 0) {
                    float er  = fminf(fmaxf(d0 * REDV, -CLIPV), CLIPV);
                    float er1 = fminf(fmaxf(d1 * REDV, -CLIPV), CLIPV);
                    int b = b0 + (lr >> 6);
                    out[((size_t)b * Kn + k) * Pn + p] = er;
                    out[(size_t)Bn * Kn * Pn + ((size_t)b * Kn + k) * Pn + p] = er1;
                    ers[lr]  = er;
                    er1s[lr] = er1;
                }
            }
        }
    }
    __syncthreads();
    if (tid < 4) {
        int bb = tid & 1;
        const float* src = (float*)(smb + ERSOF) + ((tid < 2) ? 0 : 128);
        float s = 0.f;
        #pragma unroll
        for (int p = 0; p < 64; p++) s += src[bb * 64 + p];
        if (tid < 2) f_dev[k * Bn + b0 + bb]  = s;
        else         f1_dev[k * Bn + b0 + bb] = s;
    }
    __syncthreads();

    // ---- last-CTA finalize: pull/push ----
    __threadfence();
    __shared__ u32 s_is_last;
    if (tid == 0) {
        u32 old = atomicAdd(&done_ctr, 1u);
        s_is_last = (old == gridDim.x * gridDim.y - 1) ? 1u : 0u;
    }
    __syncthreads();
    if (s_is_last) {
        __threadfence();
        float* s_pull = (float*)smb;
        float* s_push = s_pull + 128;
        float pull = 0.f, push = 0.f;
        if (tid < Kn) {
            float se = 0.f, sc = 0.f;
            int ne = 0, nc = 0;
            #pragma unroll 8
            for (int b = 0; b < Bn; b++) {
                float fv  = __ldcg(&f_dev[tid * Bn + b]);
                float f1v = __ldcg(&f1_dev[tid * Bn + b]);
                if (ycls[b] == tid) { se += f1v; ne++; }
                else if (fv < PUSHT) { sc += fv; nc++; }
            }
            if (ne > 0) pull = se / (float)ne;
            if (nc > 0) push = sc / (float)nc;
        }
        s_pull[tid] = pull;
        s_push[tid] = push;
        __syncthreads();
        for (int s = 64; s > 0; s >>= 1) {
            if (tid < s) { s_pull[tid] += s_pull[tid + s]; s_push[tid] += s_push[tid + s]; }
            __syncthreads();
        }
        if (tid == 0) {
            size_t base = (size_t)2 * Bn * Kn * Pn;
            out[base]     = s_pull[0];
            out[base + 1] = s_push[0];
            done_ctr = 0;   // deterministic across graph replays
        }
    }
}

extern "C" void kernel_launch(void* const* d_in, const int* in_sizes, int n_in,
                              void* d_out, int out_size)
{
    const float* x    = (const float*)d_in[0];
    const int*   ycls = (const int*)  d_in[1];
    const float* W1   = (const float*)d_in[4];
    const float* W2   = (const float*)d_in[5];
    const float* W3   = (const float*)d_in[6];
    const float* pr0  = (const float*)d_in[7];
    const float* pr1  = (const float*)d_in[8];
    float* out = (float*)d_out;

    permute_x<<<dim3(Bn, Cn / 64), 256>>>(x);
    permute_w1<<<1600, 256>>>(W1);
    permute_w2<<<400, 256>>>(W2);
    permute_w3<<<200, 256>>>(W3);

    cudaFuncSetAttribute(fused_main, cudaFuncAttributeMaxDynamicSharedMemorySize, SMEM_BYTES);
    fused_main<<<dim3(32, Kn), 128, SMEM_BYTES>>>(ycls, pr0, pr1, out);
}

// round 7
// speedup vs baseline: 9.4785x; 1.2002x over previous
#include <cuda_runtime.h>
#include <cstdint>

// ---------------- problem constants ----------------
#define Bn   64
#define Cn   512
#define Pn   64
#define Kn   100
#define H1n  64
#define HIDn 128
#define Ln   32
#define CLIPV 100.0f
#define REDV (-0.1f)
#define PUSHT 10000.0f

typedef unsigned int u32;

// ---------------- device scratch (bf16 fragment layouts) ----------------
__device__ uint4 xF[(size_t)256 * 32 * 32];
__device__ uint4 w1F[(size_t)Kn * 32 * 4 * 32];
__device__ uint4 w2F[(size_t)Kn * 4 * 8 * 32];
__device__ uint4 w3F[(size_t)Kn * 8 * 2 * 32];
__device__ float f_dev[Kn * Bn];
__device__ float f1_dev[Kn * Bn];
__device__ unsigned int done_ctr = 0;

// ---------------- smem regions (bytes) ----------------
#define RING0   0          // 16KB W1 ring buf0 (later h1: 4x4KB, then h2 lower)
#define RING1   16384      // 16KB W1 ring buf1 (later h2 upper)
#define W2S     32768      // 16KB
#define W3S     49152      // 8KB
#define PSS     57344      // 2 x [32][68] floats = 17408B
#define ERSOF   74752      // 256 floats
#define SMEM_BYTES 75776

// ---------------- helpers ----------------
__device__ __forceinline__ u32 smem_u32(const void* p) {
    u32 a;
    asm("{ .reg .u64 t; cvta.to.shared.u64 t, %1; cvt.u32.u64 %0, t; }" : "=r"(a) : "l"(p));
    return a;
}
__device__ __forceinline__ float tanh_fast(float x) {
    float y; asm("tanh.approx.f32 %0, %1;" : "=f"(y) : "f"(x)); return y;
}
// pack two floats to bf16x2: lo -> bits[15:0], hi -> bits[31:16]
__device__ __forceinline__ u32 pk(float lo, float hi) {
    u32 r; asm("cvt.rn.bf16x2.f32 %0, %1, %2;" : "=r"(r) : "f"(hi), "f"(lo)); return r;
}
__device__ __forceinline__ void mma_bf16(float* d, uint4 a, u32 b0, u32 b1) {
    asm volatile(
        "mma.sync.aligned.m16n8k16.row.col.f32.bf16.bf16.f32 "
        "{%0,%1,%2,%3}, {%4,%5,%6,%7}, {%8,%9}, {%0,%1,%2,%3};"
        : "+f"(d[0]), "+f"(d[1]), "+f"(d[2]), "+f"(d[3])
        : "r"(a.x), "r"(a.y), "r"(a.z), "r"(a.w), "r"(b0), "r"(b1));
}
#define CP16(saddr, gptr) \
    asm volatile("cp.async.cg.shared.global [%0], [%1], 16;" :: "r"(saddr), "l"(gptr) : "memory")
#define CP_COMMIT() asm volatile("cp.async.commit_group;" ::: "memory")
#define CP_WAIT(n)  asm volatile("cp.async.wait_group %0;" :: "n"(n) : "memory")

// ================= fused permute kernel (x, W1, W2, W3 in one launch) =================
// blocks: [0,512) permute_x ; [512,2112) w1 ; [2112,2512) w2 ; [2512,2712) w3
__global__ __launch_bounds__(256) void permute_all(const float* __restrict__ x,
                                                   const float* __restrict__ W1,
                                                   const float* __restrict__ W2,
                                                   const float* __restrict__ W3)
{
    __shared__ float t[64][65];
    const int bid = blockIdx.x;
    const int tid = threadIdx.x;

    if (bid < 512) {
        const int b = bid >> 3, cg = bid & 7;
        #pragma unroll
        for (int i = 0; i < 4; i++) {
            int idx = tid + i * 256;
            int cc = idx >> 4, p4 = (idx & 15) * 4;
            float4 v = *(const float4*)(x + ((size_t)(b * Cn + cg * 64 + cc)) * Pn + p4);
            t[cc][p4 + 0] = v.x; t[cc][p4 + 1] = v.y; t[cc][p4 + 2] = v.z; t[cc][p4 + 3] = v.w;
        }
        __syncthreads();
        #pragma unroll
        for (int i = 0; i < 2; i++) {
            int o = tid + i * 256;
            int lane = o & 31, kbl = (o >> 5) & 3, Rl = (o >> 7) & 3;
            int g = lane >> 2, tt = lane & 3;
            int c0 = kbl * 16 + 2 * tt, pA = Rl * 16 + g;
            uint4 v;
            v.x = pk(t[c0][pA],         t[c0 + 1][pA]);
            v.y = pk(t[c0][pA + 8],     t[c0 + 1][pA + 8]);
            v.z = pk(t[c0 + 8][pA],     t[c0 + 9][pA]);
            v.w = pk(t[c0 + 8][pA + 8], t[c0 + 9][pA + 8]);
            xF[((size_t)(b * 4 + Rl) * 32 + cg * 4 + kbl) * 32 + lane] = v;
        }
    } else if (bid < 2112) {
        int id = (bid - 512) * 256 + tid;            // 409600
        int lane = id & 31, np = (id >> 5) & 3, kb = (id >> 7) & 31, k = id >> 12;
        int g = lane >> 2, tt = lane & 3;
        int o0 = np * 16 + g, o1 = o0 + 8, c = kb * 16 + 2 * tt;
        const float* W = W1 + (size_t)k * H1n * Cn;
        uint4 v;
        v.x = pk(W[(size_t)o0 * Cn + c],     W[(size_t)o0 * Cn + c + 1]);
        v.y = pk(W[(size_t)o0 * Cn + c + 8], W[(size_t)o0 * Cn + c + 9]);
        v.z = pk(W[(size_t)o1 * Cn + c],     W[(size_t)o1 * Cn + c + 1]);
        v.w = pk(W[(size_t)o1 * Cn + c + 8], W[(size_t)o1 * Cn + c + 9]);
        w1F[id] = v;
    } else if (bid < 2512) {
        int id = (bid - 2112) * 256 + tid;           // 102400
        int lane = id & 31, np = (id >> 5) & 7, kb = (id >> 8) & 3, k = id >> 10;
        int g = lane >> 2, tt = lane & 3;
        int o0 = np * 16 + g, o1 = o0 + 8, c = kb * 16 + 2 * tt;
        const float* W = W2 + (size_t)k * HIDn * H1n;
        uint4 v;
        v.x = pk(W[(size_t)o0 * H1n + c],     W[(size_t)o0 * H1n + c + 1]);
        v.y = pk(W[(size_t)o0 * H1n + c + 8], W[(size_t)o0 * H1n + c + 9]);
        v.z = pk(W[(size_t)o1 * H1n + c],     W[(size_t)o1 * H1n + c + 1]);
        v.w = pk(W[(size_t)o1 * H1n + c + 8], W[(size_t)o1 * H1n + c + 9]);
        w2F[id] = v;
    } else {
        int id = (bid - 2512) * 256 + tid;           // 51200
        int lane = id & 31, np = (id >> 5) & 1, kb = (id >> 6) & 7, k = id >> 9;
        int g = lane >> 2, tt = lane & 3;
        int o0 = np * 16 + g, o1 = o0 + 8, c = kb * 16 + 2 * tt;
        const float* W = W3 + (size_t)k * Ln * HIDn;
        uint4 v;
        v.x = pk(W[(size_t)o0 * HIDn + c],     W[(size_t)o0 * HIDn + c + 1]);
        v.y = pk(W[(size_t)o0 * HIDn + c + 8], W[(size_t)o0 * HIDn + c + 9]);
        v.z = pk(W[(size_t)o1 * HIDn + c],     W[(size_t)o1 * HIDn + c + 1]);
        v.w = pk(W[(size_t)o1 * HIDn + c + 8], W[(size_t)o1 * HIDn + c + 9]);
        w3F[id] = v;
    }
}

// ================= main fused kernel: 128 threads, 4 warps, M=32/warp, 3 CTA/SM =================
__global__ __launch_bounds__(128, 3)
void fused_main(const int* __restrict__ ycls, const float* __restrict__ pr0,
                const float* __restrict__ pr1, float* __restrict__ out)
{
    extern __shared__ char smb[];
    const u32 smu = smem_u32(smb);
    const int k     = blockIdx.y;
    const int jtile = blockIdx.x;
    const int jbase = jtile * 128;
    const int b0    = jtile * 2;
    const int tid   = threadIdx.x;
    const int lane  = tid & 31;
    const int warp  = tid >> 5;
    const int g     = lane >> 2;
    const int tt    = lane & 3;

    // ---- PS fill (padded stride 68) ----
    {
        const float* p0k = pr0 + (size_t)k * Ln * Pn;
        const float* p1k = pr1 + (size_t)k * Ln * Pn;
        #pragma unroll
        for (int i = 0; i < 4; i++) {
            int idx = tid + i * 128;
            int l = idx >> 4, p4 = (idx & 15) * 4;
            *(float4*)(smb + PSS + (l * 68 + p4) * 4)        = *(const float4*)(p0k + idx * 4);
            *(float4*)(smb + PSS + (2176 + l * 68 + p4) * 4) = *(const float4*)(p1k + idx * 4);
        }
    }
    // ---- cp.async: W2 + W3; then W1 chunk 0 ----
    {
        const uint4* w2k = w2F + (size_t)k * 1024;
        const uint4* w3k = w3F + (size_t)k * 512;
        #pragma unroll
        for (int i = 0; i < 8; i++) CP16(smu + W2S + (tid + i * 128) * 16, w2k + tid + i * 128);
        #pragma unroll
        for (int i = 0; i < 4; i++) CP16(smu + W3S + (tid + i * 128) * 16, w3k + tid + i * 128);
        CP_COMMIT();
    }
    const uint4* w1k = w1F + (size_t)k * 4096;
    {
        #pragma unroll
        for (int i = 0; i < 8; i++) CP16(smu + RING0 + (tid + i * 128) * 16, w1k + tid + i * 128);
        CP_COMMIT();
    }

    // ================= Stage A: M=32/warp, N=64, K=512 (32 kb16-steps) =================
    const int R0 = jtile * 8 + warp * 2, R1 = R0 + 1;
    float accA[8][2][4];
    #pragma unroll
    for (int n = 0; n < 8; n++)
        #pragma unroll
        for (int r = 0; r < 2; r++)
            #pragma unroll
            for (int q = 0; q < 4; q++) accA[n][r][q] = 0.f;

    uint4 aA = xF[((size_t)R0 * 32 + 0) * 32 + lane];
    uint4 aB = xF[((size_t)R1 * 32 + 0) * 32 + lane];

    for (int cc = 0; cc < 4; cc++) {
        __syncthreads();
        if (cc < 3) {
            u32 dst = smu + ((cc + 1) & 1) * 16384;
            const uint4* src = w1k + (cc + 1) * 1024;
            #pragma unroll
            for (int i = 0; i < 8; i++) CP16(dst + (tid + i * 128) * 16, src + tid + i * 128);
            CP_COMMIT();
            CP_WAIT(1);
        } else {
            CP_WAIT(0);
        }
        __syncthreads();
        const char* rb = smb + (cc & 1) * 16384;
        #pragma unroll
        for (int ks = 0; ks < 8; ks++) {
            int kb = cc * 8 + ks;
            uint4 nA = aA, nB = aB;
            if (kb < 31) {
                nA = xF[((size_t)R0 * 32 + kb + 1) * 32 + lane];
                nB = xF[((size_t)R1 * 32 + kb + 1) * 32 + lane];
            }
            #pragma unroll
            for (int np = 0; np < 4; np++) {
                uint4 bv = *(const uint4*)(rb + ((ks * 4 + np) * 32 + lane) * 16);
                mma_bf16(accA[2 * np][0],     aA, bv.x, bv.y);
                mma_bf16(accA[2 * np][1],     aB, bv.x, bv.y);
                mma_bf16(accA[2 * np + 1][0], aA, bv.z, bv.w);
                mma_bf16(accA[2 * np + 1][1], aB, bv.z, bv.w);
            }
            aA = nA; aB = nB;
        }
    }

    // ---- epilogue A: tanh -> bf16x2 -> h1 (warp-private [32 rows][32 words], rotated) ----
    {
        u32* h1 = (u32*)(smb + warp * 4096);
        #pragma unroll
        for (int n0 = 0; n0 < 8; n0++) {
            int cA = (n0 * 4 + tt + 4 * g) & 31;
            #pragma unroll
            for (int rt = 0; rt < 2; rt++) {
                int row = rt * 16 + g;
                h1[row * 32 + cA]       = pk(tanh_fast(accA[n0][rt][0]), tanh_fast(accA[n0][rt][1]));
                h1[(row + 8) * 32 + cA] = pk(tanh_fast(accA[n0][rt][2]), tanh_fast(accA[n0][rt][3]));
            }
        }
    }
    __syncwarp();

    // ================= Stage B: M=32, N=128, K=64 (4 kb16-steps) =================
    float accB[16][2][4];
    #pragma unroll
    for (int n = 0; n < 16; n++)
        #pragma unroll
        for (int r = 0; r < 2; r++)
            #pragma unroll
            for (int q = 0; q < 4; q++) accB[n][r][q] = 0.f;
    {
        const u32* h1 = (const u32*)(smb + warp * 4096);
        #pragma unroll
        for (int kb = 0; kb < 4; kb++) {
            int cx = (kb * 8 + tt + 4 * g) & 31;
            int cz = (kb * 8 + tt + 4 + 4 * g) & 31;
            uint4 af[2];
            #pragma unroll
            for (int rt = 0; rt < 2; rt++) {
                int row = rt * 16 + g;
                af[rt].x = h1[row * 32 + cx];
                af[rt].y = h1[(row + 8) * 32 + cx];
                af[rt].z = h1[row * 32 + cz];
                af[rt].w = h1[(row + 8) * 32 + cz];
            }
            #pragma unroll
            for (int np = 0; np < 8; np++) {
                uint4 bv = *(const uint4*)(smb + W2S + ((kb * 8 + np) * 32 + lane) * 16);
                mma_bf16(accB[2 * np][0],     af[0], bv.x, bv.y);
                mma_bf16(accB[2 * np][1],     af[1], bv.x, bv.y);
                mma_bf16(accB[2 * np + 1][0], af[0], bv.z, bv.w);
                mma_bf16(accB[2 * np + 1][1], af[1], bv.z, bv.w);
            }
        }
    }
    __syncthreads();                             // h2 overlays ring + all h1

    // ---- epilogue B: tanh -> bf16x2 -> h2 (warp-private [32 rows][64 words], rotated) ----
    {
        u32* h2 = (u32*)(smb + warp * 8192);
        #pragma unroll
        for (int n0 = 0; n0 < 16; n0++) {
            int cB = (n0 * 4 + tt + 4 * g) & 63;
            #pragma unroll
            for (int rt = 0; rt < 2; rt++) {
                int row = rt * 16 + g;
                h2[row * 64 + cB]       = pk(tanh_fast(accB[n0][rt][0]), tanh_fast(accB[n0][rt][1]));
                h2[(row + 8) * 64 + cB] = pk(tanh_fast(accB[n0][rt][2]), tanh_fast(accB[n0][rt][3]));
            }
        }
    }
    __syncwarp();

    // ================= Stage C: M=32, N=32, K=128 (8 kb16-steps) =================
    float accC[4][2][4];
    #pragma unroll
    for (int n = 0; n < 4; n++)
        #pragma unroll
        for (int r = 0; r < 2; r++)
            #pragma unroll
            for (int q = 0; q < 4; q++) accC[n][r][q] = 0.f;
    {
        const u32* h2 = (const u32*)(smb + warp * 8192);
        #pragma unroll
        for (int kb = 0; kb < 8; kb++) {
            int cx = (kb * 8 + tt + 4 * g) & 63;
            int cz = (kb * 8 + tt + 4 + 4 * g) & 63;
            uint4 af[2];
            #pragma unroll
            for (int rt = 0; rt < 2; rt++) {
                int row = rt * 16 + g;
                af[rt].x = h2[row * 64 + cx];
                af[rt].y = h2[(row + 8) * 64 + cx];
                af[rt].z = h2[row * 64 + cz];
                af[rt].w = h2[(row + 8) * 64 + cz];
            }
            #pragma unroll
            for (int np = 0; np < 2; np++) {
                uint4 bv = *(const uint4*)(smb + W3S + ((kb * 2 + np) * 32 + lane) * 16);
                mma_bf16(accC[2 * np][0],     af[0], bv.x, bv.y);
                mma_bf16(accC[2 * np][1],     af[1], bv.x, bv.y);
                mma_bf16(accC[2 * np + 1][0], af[0], bv.z, bv.w);
                mma_bf16(accC[2 * np + 1][1], af[1], bv.z, bv.w);
            }
        }
    }

    // ---- epilogue C: tanh, distances, clip, logits, per-(k,b) sums ----
    {
        const float* ps0 = (const float*)(smb + PSS);
        const float* ps1 = ps0 + 2176;
        float* ers  = (float*)(smb + ERSOF);
        float* er1s = ers + 128;
        #pragma unroll
        for (int rt = 0; rt < 2; rt++) {
            #pragma unroll
            for (int half = 0; half < 2; half++) {
                int lr = warp * 32 + rt * 16 + g + half * 8;
                int p  = (jbase + lr) & 63;
                float d0 = 0.f, d1 = 0.f;
                #pragma unroll
                for (int n0 = 0; n0 < 4; n0++) {
                    int c0 = n0 * 8 + 2 * tt, c1 = c0 + 1;
                    float v0 = tanh_fast(accC[n0][rt][half * 2 + 0]);
                    float v1 = tanh_fast(accC[n0][rt][half * 2 + 1]);
                    float q;
                    q = v0 - ps0[c0 * 68 + p]; d0 += q * q;
                    q = v1 - ps0[c1 * 68 + p]; d0 += q * q;
                    q = v0 - ps1[c0 * 68 + p]; d1 += q * q;
                    q = v1 - ps1[c1 * 68 + p]; d1 += q * q;
                }
                d0 += __shfl_xor_sync(0xFFFFFFFFu, d0, 1);
                d0 += __shfl_xor_sync(0xFFFFFFFFu, d0, 2);
                d1 += __shfl_xor_sync(0xFFFFFFFFu, d1, 1);
                d1 += __shfl_xor_sync(0xFFFFFFFFu, d1, 2);
                if (tt == 0) {
                    float er  = fminf(fmaxf(d0 * REDV, -CLIPV), CLIPV);
                    float er1 = fminf(fmaxf(d1 * REDV, -CLIPV), CLIPV);
                    int b = b0 + (lr >> 6);
                    out[((size_t)b * Kn + k) * Pn + p] = er;
                    out[(size_t)Bn * Kn * Pn + ((size_t)b * Kn + k) * Pn + p] = er1;
                    ers[lr]  = er;
                    er1s[lr] = er1;
                }
            }
        }
    }
    __syncthreads();
    if (tid < 4) {
        int bb = tid & 1;
        const float* src = (float*)(smb + ERSOF) + ((tid < 2) ? 0 : 128);
        float s = 0.f;
        #pragma unroll
        for (int p = 0; p < 64; p++) s += src[bb * 64 + p];
        if (tid < 2) f_dev[k * Bn + b0 + bb]  = s;
        else         f1_dev[k * Bn + b0 + bb] = s;
    }
    __syncthreads();

    // ---- last-CTA finalize: pull/push ----
    __threadfence();
    __shared__ u32 s_is_last;
    if (tid == 0) {
        u32 old = atomicAdd(&done_ctr, 1u);
        s_is_last = (old == gridDim.x * gridDim.y - 1) ? 1u : 0u;
    }
    __syncthreads();
    if (s_is_last) {
        __threadfence();
        float* s_pull = (float*)smb;
        float* s_push = s_pull + 128;
        float pull = 0.f, push = 0.f;
        if (tid < Kn) {
            float se = 0.f, sc = 0.f;
            int ne = 0, nc = 0;
            #pragma unroll 8
            for (int b = 0; b < Bn; b++) {
                float fv  = __ldcg(&f_dev[tid * Bn + b]);
                float f1v = __ldcg(&f1_dev[tid * Bn + b]);
                if (ycls[b] == tid) { se += f1v; ne++; }
                else if (fv < PUSHT) { sc += fv; nc++; }
            }
            if (ne > 0) pull = se / (float)ne;
            if (nc > 0) push = sc / (float)nc;
        }
        s_pull[tid] = pull;
        s_push[tid] = push;
        __syncthreads();
        for (int s = 64; s > 0; s >>= 1) {
            if (tid < s) { s_pull[tid] += s_pull[tid + s]; s_push[tid] += s_push[tid + s]; }
            __syncthreads();
        }
        if (tid == 0) {
            size_t base = (size_t)2 * Bn * Kn * Pn;
            out[base]     = s_pull[0];
            out[base + 1] = s_push[0];
            done_ctr = 0;   // deterministic across graph replays
        }
    }
}

extern "C" void kernel_launch(void* const* d_in, const int* in_sizes, int n_in,
                              void* d_out, int out_size)
{
    const float* x    = (const float*)d_in[0];
    const int*   ycls = (const int*)  d_in[1];
    const float* W1   = (const float*)d_in[4];
    const float* W2   = (const float*)d_in[5];
    const float* W3   = (const float*)d_in[6];
    const float* pr0  = (const float*)d_in[7];
    const float* pr1  = (const float*)d_in[8];
    float* out = (float*)d_out;

    permute_all<<<2712, 256>>>(x, W1, W2, W3);

    cudaFuncSetAttribute(fused_main, cudaFuncAttributeMaxDynamicSharedMemorySize, SMEM_BYTES);
    fused_main<<<dim3(32, Kn), 128, SMEM_BYTES>>>(ycls, pr0, pr1, out);
}

// round 8
// speedup vs baseline: 10.0349x; 1.0587x over previous
#include <cuda_runtime.h>
#include <cstdint>

// ---------------- problem constants ----------------
#define Bn   64
#define Cn   512
#define Pn   64
#define Kn   100
#define H1n  64
#define HIDn 128
#define Ln   32
#define CLIPV 100.0f
#define REDV (-0.1f)
#define PUSHT 10000.0f

typedef unsigned int u32;

// ---------------- device scratch (bf16 fragment layouts) ----------------
__device__ uint4 xF[(size_t)256 * 32 * 32];
__device__ uint4 w1F[(size_t)Kn * 32 * 4 * 32];
__device__ uint4 w2F[(size_t)Kn * 4 * 8 * 32];
__device__ uint4 w3F[(size_t)Kn * 8 * 2 * 32];
__device__ float f_dev[Kn * Bn];
__device__ float f1_dev[Kn * Bn];
__device__ unsigned int done_ctr = 0;

// ---------------- smem regions (bytes) ----------------
#define RING0   0          // 16KB W1 ring buf0
#define RING1   16384      // 16KB W1 ring buf1
#define W2S     32768      // 16KB
#define W3S     49152      // 8KB
#define PSS     57344      // 2 x [32][68] floats = 17408B
#define ERSOF   74752      // 256 floats
#define SMEM_BYTES 75776

// ---------------- helpers ----------------
__device__ __forceinline__ u32 smem_u32(const void* p) {
    u32 a;
    asm("{ .reg .u64 t; cvta.to.shared.u64 t, %1; cvt.u32.u64 %0, t; }" : "=r"(a) : "l"(p));
    return a;
}
__device__ __forceinline__ float tanh_fast(float x) {
    float y; asm("tanh.approx.f32 %0, %1;" : "=f"(y) : "f"(x)); return y;
}
// pack two floats to bf16x2: lo -> bits[15:0], hi -> bits[31:16]
__device__ __forceinline__ u32 pk(float lo, float hi) {
    u32 r; asm("cvt.rn.bf16x2.f32 %0, %1, %2;" : "=r"(r) : "f"(hi), "f"(lo)); return r;
}
__device__ __forceinline__ void mma_bf16(float* d, uint4 a, u32 b0, u32 b1) {
    asm volatile(
        "mma.sync.aligned.m16n8k16.row.col.f32.bf16.bf16.f32 "
        "{%0,%1,%2,%3}, {%4,%5,%6,%7}, {%8,%9}, {%0,%1,%2,%3};"
        : "+f"(d[0]), "+f"(d[1]), "+f"(d[2]), "+f"(d[3])
        : "r"(a.x), "r"(a.y), "r"(a.z), "r"(a.w), "r"(b0), "r"(b1));
}
// D-frag (4 floats x 2 adjacent n8-tiles) -> next-stage A-frag, with tanh
__device__ __forceinline__ uint4 dfrag_to_afrag(const float* dE, const float* dO) {
    uint4 a;
    a.x = pk(tanh_fast(dE[0]), tanh_fast(dE[1]));
    a.y = pk(tanh_fast(dE[2]), tanh_fast(dE[3]));
    a.z = pk(tanh_fast(dO[0]), tanh_fast(dO[1]));
    a.w = pk(tanh_fast(dO[2]), tanh_fast(dO[3]));
    return a;
}
#define CP16(saddr, gptr) \
    asm volatile("cp.async.cg.shared.global [%0], [%1], 16;" :: "r"(saddr), "l"(gptr) : "memory")
#define CP_COMMIT() asm volatile("cp.async.commit_group;" ::: "memory")
#define CP_WAIT(n)  asm volatile("cp.async.wait_group %0;" :: "n"(n) : "memory")

// ================= fused permute kernel (x, W1, W2, W3 in one launch) =================
__global__ __launch_bounds__(256) void permute_all(const float* __restrict__ x,
                                                   const float* __restrict__ W1,
                                                   const float* __restrict__ W2,
                                                   const float* __restrict__ W3)
{
    __shared__ float t[64][65];
    const int bid = blockIdx.x;
    const int tid = threadIdx.x;

    if (bid < 512) {
        const int b = bid >> 3, cg = bid & 7;
        #pragma unroll
        for (int i = 0; i < 4; i++) {
            int idx = tid + i * 256;
            int cc = idx >> 4, p4 = (idx & 15) * 4;
            float4 v = *(const float4*)(x + ((size_t)(b * Cn + cg * 64 + cc)) * Pn + p4);
            t[cc][p4 + 0] = v.x; t[cc][p4 + 1] = v.y; t[cc][p4 + 2] = v.z; t[cc][p4 + 3] = v.w;
        }
        __syncthreads();
        #pragma unroll
        for (int i = 0; i < 2; i++) {
            int o = tid + i * 256;
            int lane = o & 31, kbl = (o >> 5) & 3, Rl = (o >> 7) & 3;
            int g = lane >> 2, tt = lane & 3;
            int c0 = kbl * 16 + 2 * tt, pA = Rl * 16 + g;
            uint4 v;
            v.x = pk(t[c0][pA],         t[c0 + 1][pA]);
            v.y = pk(t[c0][pA + 8],     t[c0 + 1][pA + 8]);
            v.z = pk(t[c0 + 8][pA],     t[c0 + 9][pA]);
            v.w = pk(t[c0 + 8][pA + 8], t[c0 + 9][pA + 8]);
            xF[((size_t)(b * 4 + Rl) * 32 + cg * 4 + kbl) * 32 + lane] = v;
        }
    } else if (bid < 2112) {
        int id = (bid - 512) * 256 + tid;
        int lane = id & 31, np = (id >> 5) & 3, kb = (id >> 7) & 31, k = id >> 12;
        int g = lane >> 2, tt = lane & 3;
        int o0 = np * 16 + g, o1 = o0 + 8, c = kb * 16 + 2 * tt;
        const float* W = W1 + (size_t)k * H1n * Cn;
        uint4 v;
        v.x = pk(W[(size_t)o0 * Cn + c],     W[(size_t)o0 * Cn + c + 1]);
        v.y = pk(W[(size_t)o0 * Cn + c + 8], W[(size_t)o0 * Cn + c + 9]);
        v.z = pk(W[(size_t)o1 * Cn + c],     W[(size_t)o1 * Cn + c + 1]);
        v.w = pk(W[(size_t)o1 * Cn + c + 8], W[(size_t)o1 * Cn + c + 9]);
        w1F[id] = v;
    } else if (bid < 2512) {
        int id = (bid - 2112) * 256 + tid;
        int lane = id & 31, np = (id >> 5) & 7, kb = (id >> 8) & 3, k = id >> 10;
        int g = lane >> 2, tt = lane & 3;
        int o0 = np * 16 + g, o1 = o0 + 8, c = kb * 16 + 2 * tt;
        const float* W = W2 + (size_t)k * HIDn * H1n;
        uint4 v;
        v.x = pk(W[(size_t)o0 * H1n + c],     W[(size_t)o0 * H1n + c + 1]);
        v.y = pk(W[(size_t)o0 * H1n + c + 8], W[(size_t)o0 * H1n + c + 9]);
        v.z = pk(W[(size_t)o1 * H1n + c],     W[(size_t)o1 * H1n + c + 1]);
        v.w = pk(W[(size_t)o1 * H1n + c + 8], W[(size_t)o1 * H1n + c + 9]);
        w2F[id] = v;
    } else {
        int id = (bid - 2512) * 256 + tid;
        int lane = id & 31, np = (id >> 5) & 1, kb = (id >> 6) & 7, k = id >> 9;
        int g = lane >> 2, tt = lane & 3;
        int o0 = np * 16 + g, o1 = o0 + 8, c = kb * 16 + 2 * tt;
        const float* W = W3 + (size_t)k * Ln * HIDn;
        uint4 v;
        v.x = pk(W[(size_t)o0 * HIDn + c],     W[(size_t)o0 * HIDn + c + 1]);
        v.y = pk(W[(size_t)o0 * HIDn + c + 8], W[(size_t)o0 * HIDn + c + 9]);
        v.z = pk(W[(size_t)o1 * HIDn + c],     W[(size_t)o1 * HIDn + c + 1]);
        v.w = pk(W[(size_t)o1 * HIDn + c + 8], W[(size_t)o1 * HIDn + c + 9]);
        w3F[id] = v;
    }
}

// ================= main fused kernel: 128 threads, 4 warps, fully register-fused =================
__global__ __launch_bounds__(128, 3)
void fused_main(const int* __restrict__ ycls, const float* __restrict__ pr0,
                const float* __restrict__ pr1, float* __restrict__ out)
{
    extern __shared__ char smb[];
    const u32 smu = smem_u32(smb);
    const int k     = blockIdx.y;
    const int jtile = blockIdx.x;
    const int jbase = jtile * 128;
    const int b0    = jtile * 2;
    const int tid   = threadIdx.x;
    const int lane  = tid & 31;
    const int warp  = tid >> 5;
    const int g     = lane >> 2;
    const int tt    = lane & 3;

    // ---- PS fill (padded stride 68) ----
    {
        const float* p0k = pr0 + (size_t)k * Ln * Pn;
        const float* p1k = pr1 + (size_t)k * Ln * Pn;
        #pragma unroll
        for (int i = 0; i < 4; i++) {
            int idx = tid + i * 128;
            int l = idx >> 4, p4 = (idx & 15) * 4;
            *(float4*)(smb + PSS + (l * 68 + p4) * 4)        = *(const float4*)(p0k + idx * 4);
            *(float4*)(smb + PSS + (2176 + l * 68 + p4) * 4) = *(const float4*)(p1k + idx * 4);
        }
    }
    // ---- cp.async: W2 + W3 group; then W1 chunk 0 ----
    {
        const uint4* w2k = w2F + (size_t)k * 1024;
        const uint4* w3k = w3F + (size_t)k * 512;
        #pragma unroll
        for (int i = 0; i < 8; i++) CP16(smu + W2S + (tid + i * 128) * 16, w2k + tid + i * 128);
        #pragma unroll
        for (int i = 0; i < 4; i++) CP16(smu + W3S + (tid + i * 128) * 16, w3k + tid + i * 128);
        CP_COMMIT();
    }
    const uint4* w1k = w1F + (size_t)k * 4096;
    {
        #pragma unroll
        for (int i = 0; i < 8; i++) CP16(smu + RING0 + (tid + i * 128) * 16, w1k + tid + i * 128);
        CP_COMMIT();
    }

    // ================= Stage A: M=32/warp, N=64, K=512 (one barrier per chunk) =================
    const int R0 = jtile * 8 + warp * 2, R1 = R0 + 1;
    float accA[8][2][4];
    #pragma unroll
    for (int n = 0; n < 8; n++)
        #pragma unroll
        for (int r = 0; r < 2; r++)
            #pragma unroll
            for (int q = 0; q < 4; q++) accA[n][r][q] = 0.f;

    uint4 aA = xF[((size_t)R0 * 32 + 0) * 32 + lane];
    uint4 aB = xF[((size_t)R1 * 32 + 0) * 32 + lane];

    for (int cc = 0; cc < 4; cc++) {
        CP_WAIT(0);                              // current buf (cc&1) loaded
        __syncthreads();                         // + all warps done reading buf being overwritten
        if (cc < 3) {
            u32 dst = smu + ((cc + 1) & 1) * 16384;
            const uint4* src = w1k + (cc + 1) * 1024;
            #pragma unroll
            for (int i = 0; i < 8; i++) CP16(dst + (tid + i * 128) * 16, src + tid + i * 128);
            CP_COMMIT();
        }
        const char* rb = smb + (cc & 1) * 16384;
        #pragma unroll
        for (int ks = 0; ks < 8; ks++) {
            int kb = cc * 8 + ks;
            uint4 nA = aA, nB = aB;
            if (kb < 31) {
                nA = xF[((size_t)R0 * 32 + kb + 1) * 32 + lane];
                nB = xF[((size_t)R1 * 32 + kb + 1) * 32 + lane];
            }
            #pragma unroll
            for (int np = 0; np < 4; np++) {
                uint4 bv = *(const uint4*)(rb + ((ks * 4 + np) * 32 + lane) * 16);
                mma_bf16(accA[2 * np][0],     aA, bv.x, bv.y);
                mma_bf16(accA[2 * np][1],     aB, bv.x, bv.y);
                mma_bf16(accA[2 * np + 1][0], aA, bv.z, bv.w);
                mma_bf16(accA[2 * np + 1][1], aB, bv.z, bv.w);
            }
            aA = nA; aB = nB;
        }
    }

    // ---- h1 A-frags built in registers (no smem round-trip) ----
    uint4 h1f[2][4];                             // [rt][kb] over K=64
    #pragma unroll
    for (int rt = 0; rt < 2; rt++)
        #pragma unroll
        for (int kb = 0; kb < 4; kb++)
            h1f[rt][kb] = dfrag_to_afrag(accA[2 * kb][rt], accA[2 * kb + 1][rt]);

    // ================= Stages B+C fused: h2 in 4 N-slices, never in smem =================
    float accC[4][2][4];
    #pragma unroll
    for (int n = 0; n < 4; n++)
        #pragma unroll
        for (int r = 0; r < 2; r++)
            #pragma unroll
            for (int q = 0; q < 4; q++) accC[n][r][q] = 0.f;

    #pragma unroll
    for (int s = 0; s < 4; s++) {
        // ---- stage B slice: N=32 (h2 cols [32s, 32s+32)), K=64 ----
        float accB[4][2][4];
        #pragma unroll
        for (int n = 0; n < 4; n++)
            #pragma unroll
            for (int r = 0; r < 2; r++)
                #pragma unroll
                for (int q = 0; q < 4; q++) accB[n][r][q] = 0.f;
        #pragma unroll
        for (int kb = 0; kb < 4; kb++) {
            uint4 bv0 = *(const uint4*)(smb + W2S + ((kb * 8 + 2 * s) * 32 + lane) * 16);
            uint4 bv1 = *(const uint4*)(smb + W2S + ((kb * 8 + 2 * s + 1) * 32 + lane) * 16);
            #pragma unroll
            for (int rt = 0; rt < 2; rt++) {
                mma_bf16(accB[0][rt], h1f[rt][kb], bv0.x, bv0.y);
                mma_bf16(accB[1][rt], h1f[rt][kb], bv0.z, bv0.w);
                mma_bf16(accB[2][rt], h1f[rt][kb], bv1.x, bv1.y);
                mma_bf16(accB[3][rt], h1f[rt][kb], bv1.z, bv1.w);
            }
        }
        // ---- pack slice as stage-C A-frags (K-chunks 2s, 2s+1) and accumulate C ----
        #pragma unroll
        for (int kb2 = 0; kb2 < 2; kb2++) {
            int kbC = 2 * s + kb2;
            uint4 bw0 = *(const uint4*)(smb + W3S + ((kbC * 2 + 0) * 32 + lane) * 16);
            uint4 bw1 = *(const uint4*)(smb + W3S + ((kbC * 2 + 1) * 32 + lane) * 16);
            #pragma unroll
            for (int rt = 0; rt < 2; rt++) {
                uint4 af = dfrag_to_afrag(accB[2 * kb2][rt], accB[2 * kb2 + 1][rt]);
                mma_bf16(accC[0][rt], af, bw0.x, bw0.y);
                mma_bf16(accC[1][rt], af, bw0.z, bw0.w);
                mma_bf16(accC[2][rt], af, bw1.x, bw1.y);
                mma_bf16(accC[3][rt], af, bw1.z, bw1.w);
            }
        }
    }

    // ---- epilogue C: tanh, distances, clip, logits, per-(k,b) sums ----
    {
        const float* ps0 = (const float*)(smb + PSS);
        const float* ps1 = ps0 + 2176;
        float* ers  = (float*)(smb + ERSOF);
        float* er1s = ers + 128;
        #pragma unroll
        for (int rt = 0; rt < 2; rt++) {
            #pragma unroll
            for (int half = 0; half < 2; half++) {
                int lr = warp * 32 + rt * 16 + g + half * 8;
                int p  = (jbase + lr) & 63;
                float d0 = 0.f, d1 = 0.f;
                #pragma unroll
                for (int n0 = 0; n0 < 4; n0++) {
                    int c0 = n0 * 8 + 2 * tt, c1 = c0 + 1;
                    float v0 = tanh_fast(accC[n0][rt][half * 2 + 0]);
                    float v1 = tanh_fast(accC[n0][rt][half * 2 + 1]);
                    float q;
                    q = v0 - ps0[c0 * 68 + p]; d0 += q * q;
                    q = v1 - ps0[c1 * 68 + p]; d0 += q * q;
                    q = v0 - ps1[c0 * 68 + p]; d1 += q * q;
                    q = v1 - ps1[c1 * 68 + p]; d1 += q * q;
                }
                d0 += __shfl_xor_sync(0xFFFFFFFFu, d0, 1);
                d0 += __shfl_xor_sync(0xFFFFFFFFu, d0, 2);
                d1 += __shfl_xor_sync(0xFFFFFFFFu, d1, 1);
                d1 += __shfl_xor_sync(0xFFFFFFFFu, d1, 2);
                if (tt == 0) {
                    float er  = fminf(fmaxf(d0 * REDV, -CLIPV), CLIPV);
                    float er1 = fminf(fmaxf(d1 * REDV, -CLIPV), CLIPV);
                    int b = b0 + (lr >> 6);
                    out[((size_t)b * Kn + k) * Pn + p] = er;
                    out[(size_t)Bn * Kn * Pn + ((size_t)b * Kn + k) * Pn + p] = er1;
                    ers[lr]  = er;
                    er1s[lr] = er1;
                }
            }
        }
    }
    __syncthreads();
    if (tid < 4) {
        int bb = tid & 1;
        const float* src = (float*)(smb + ERSOF) + ((tid < 2) ? 0 : 128);
        float s = 0.f;
        #pragma unroll
        for (int p = 0; p < 64; p++) s += src[bb * 64 + p];
        if (tid < 2) f_dev[k * Bn + b0 + bb]  = s;
        else         f1_dev[k * Bn + b0 + bb] = s;
    }
    __syncthreads();

    // ---- last-CTA finalize: pull/push ----
    __threadfence();
    __shared__ u32 s_is_last;
    if (tid == 0) {
        u32 old = atomicAdd(&done_ctr, 1u);
        s_is_last = (old == gridDim.x * gridDim.y - 1) ? 1u : 0u;
    }
    __syncthreads();
    if (s_is_last) {
        __threadfence();
        float* s_pull = (float*)smb;
        float* s_push = s_pull + 128;
        float pull = 0.f, push = 0.f;
        if (tid < Kn) {
            float se = 0.f, sc = 0.f;
            int ne = 0, nc = 0;
            #pragma unroll 8
            for (int b = 0; b < Bn; b++) {
                float fv  = __ldcg(&f_dev[tid * Bn + b]);
                float f1v = __ldcg(&f1_dev[tid * Bn + b]);
                if (ycls[b] == tid) { se += f1v; ne++; }
                else if (fv < PUSHT) { sc += fv; nc++; }
            }
            if (ne > 0) pull = se / (float)ne;
            if (nc > 0) push = sc / (float)nc;
        }
        s_pull[tid] = pull;
        s_push[tid] = push;
        __syncthreads();
        for (int s = 64; s > 0; s >>= 1) {
            if (tid < s) { s_pull[tid] += s_pull[tid + s]; s_push[tid] += s_push[tid + s]; }
            __syncthreads();
        }
        if (tid == 0) {
            size_t base = (size_t)2 * Bn * Kn * Pn;
            out[base]     = s_pull[0];
            out[base + 1] = s_push[0];
            done_ctr = 0;   // deterministic across graph replays
        }
    }
}

extern "C" void kernel_launch(void* const* d_in, const int* in_sizes, int n_in,
                              void* d_out, int out_size)
{
    const float* x    = (const float*)d_in[0];
    const int*   ycls = (const int*)  d_in[1];
    const float* W1   = (const float*)d_in[4];
    const float* W2   = (const float*)d_in[5];
    const float* W3   = (const float*)d_in[6];
    const float* pr0  = (const float*)d_in[7];
    const float* pr1  = (const float*)d_in[8];
    float* out = (float*)d_out;

    permute_all<<<2712, 256>>>(x, W1, W2, W3);

    cudaFuncSetAttribute(fused_main, cudaFuncAttributeMaxDynamicSharedMemorySize, SMEM_BYTES);
    fused_main<<<dim3(32, Kn), 128, SMEM_BYTES>>>(ycls, pr0, pr1, out);
}

// round 9
// speedup vs baseline: 11.3428x; 1.1303x over previous
#include <cuda_runtime.h>
#include <cstdint>

// ---------------- problem constants ----------------
#define Bn   64
#define Cn   512
#define Pn   64
#define Kn   100
#define H1n  64
#define HIDn 128
#define Ln   32
#define CLIPV 100.0f
#define REDV (-0.1f)
#define PUSHT 10000.0f

typedef unsigned int u32;

// ---------------- device scratch (bf16 fragment layouts) ----------------
__device__ uint4 xF[(size_t)256 * 32 * 32];
__device__ uint4 w1F[(size_t)Kn * 32 * 4 * 32];
__device__ uint4 w2F[(size_t)Kn * 4 * 8 * 32];
__device__ uint4 w3F[(size_t)Kn * 8 * 2 * 32];
__device__ float f_dev[Kn * Bn];
__device__ float f1_dev[Kn * Bn];
__device__ unsigned int done_ctr = 0;

// ---------------- smem regions (bytes), 40KB total -> 4 CTAs/SM ----------------
#define RING0   0          // 8KB W1 ring buf0   | after stage A: ps0 (8KB fp32 [32][64])
#define RING1   8192       // 8KB W1 ring buf1   | after stage A: ps1
#define W2S     16384      // 16KB               | after B+C: ers/er1s (1KB)
#define W3S     32768      // 8KB
#define SMEM_BYTES 40960

// ---------------- helpers ----------------
__device__ __forceinline__ u32 smem_u32(const void* p) {
    u32 a;
    asm("{ .reg .u64 t; cvta.to.shared.u64 t, %1; cvt.u32.u64 %0, t; }" : "=r"(a) : "l"(p));
    return a;
}
__device__ __forceinline__ float tanh_fast(float x) {
    float y; asm("tanh.approx.f32 %0, %1;" : "=f"(y) : "f"(x)); return y;
}
// pack two floats to bf16x2: lo -> bits[15:0], hi -> bits[31:16]
__device__ __forceinline__ u32 pk(float lo, float hi) {
    u32 r; asm("cvt.rn.bf16x2.f32 %0, %1, %2;" : "=r"(r) : "f"(hi), "f"(lo)); return r;
}
__device__ __forceinline__ void mma_bf16(float* d, uint4 a, u32 b0, u32 b1) {
    asm volatile(
        "mma.sync.aligned.m16n8k16.row.col.f32.bf16.bf16.f32 "
        "{%0,%1,%2,%3}, {%4,%5,%6,%7}, {%8,%9}, {%0,%1,%2,%3};"
        : "+f"(d[0]), "+f"(d[1]), "+f"(d[2]), "+f"(d[3])
        : "r"(a.x), "r"(a.y), "r"(a.z), "r"(a.w), "r"(b0), "r"(b1));
}
// D-frag (4 floats x 2 adjacent n8-tiles) -> next-stage A-frag, with tanh
__device__ __forceinline__ uint4 dfrag_to_afrag(const float* dE, const float* dO) {
    uint4 a;
    a.x = pk(tanh_fast(dE[0]), tanh_fast(dE[1]));
    a.y = pk(tanh_fast(dE[2]), tanh_fast(dE[3]));
    a.z = pk(tanh_fast(dO[0]), tanh_fast(dO[1]));
    a.w = pk(tanh_fast(dO[2]), tanh_fast(dO[3]));
    return a;
}
#define CP16(saddr, gptr) \
    asm volatile("cp.async.cg.shared.global [%0], [%1], 16;" :: "r"(saddr), "l"(gptr) : "memory")
#define CP_COMMIT() asm volatile("cp.async.commit_group;" ::: "memory")
#define CP_WAIT(n)  asm volatile("cp.async.wait_group %0;" :: "n"(n) : "memory")

// ================= fused permute kernel (x, W1, W2, W3 in one launch) =================
__global__ __launch_bounds__(256) void permute_all(const float* __restrict__ x,
                                                   const float* __restrict__ W1,
                                                   const float* __restrict__ W2,
                                                   const float* __restrict__ W3)
{
    __shared__ float t[64][65];
    const int bid = blockIdx.x;
    const int tid = threadIdx.x;

    if (bid < 512) {
        const int b = bid >> 3, cg = bid & 7;
        #pragma unroll
        for (int i = 0; i < 4; i++) {
            int idx = tid + i * 256;
            int cc = idx >> 4, p4 = (idx & 15) * 4;
            float4 v = *(const float4*)(x + ((size_t)(b * Cn + cg * 64 + cc)) * Pn + p4);
            t[cc][p4 + 0] = v.x; t[cc][p4 + 1] = v.y; t[cc][p4 + 2] = v.z; t[cc][p4 + 3] = v.w;
        }
        __syncthreads();
        #pragma unroll
        for (int i = 0; i < 2; i++) {
            int o = tid + i * 256;
            int lane = o & 31, kbl = (o >> 5) & 3, Rl = (o >> 7) & 3;
            int g = lane >> 2, tt = lane & 3;
            int c0 = kbl * 16 + 2 * tt, pA = Rl * 16 + g;
            uint4 v;
            v.x = pk(t[c0][pA],         t[c0 + 1][pA]);
            v.y = pk(t[c0][pA + 8],     t[c0 + 1][pA + 8]);
            v.z = pk(t[c0 + 8][pA],     t[c0 + 9][pA]);
            v.w = pk(t[c0 + 8][pA + 8], t[c0 + 9][pA + 8]);
            xF[((size_t)(b * 4 + Rl) * 32 + cg * 4 + kbl) * 32 + lane] = v;
        }
    } else if (bid < 2112) {
        int id = (bid - 512) * 256 + tid;
        int lane = id & 31, np = (id >> 5) & 3, kb = (id >> 7) & 31, k = id >> 12;
        int g = lane >> 2, tt = lane & 3;
        int o0 = np * 16 + g, o1 = o0 + 8, c = kb * 16 + 2 * tt;
        const float* W = W1 + (size_t)k * H1n * Cn;
        uint4 v;
        v.x = pk(W[(size_t)o0 * Cn + c],     W[(size_t)o0 * Cn + c + 1]);
        v.y = pk(W[(size_t)o0 * Cn + c + 8], W[(size_t)o0 * Cn + c + 9]);
        v.z = pk(W[(size_t)o1 * Cn + c],     W[(size_t)o1 * Cn + c + 1]);
        v.w = pk(W[(size_t)o1 * Cn + c + 8], W[(size_t)o1 * Cn + c + 9]);
        w1F[id] = v;
    } else if (bid < 2512) {
        int id = (bid - 2112) * 256 + tid;
        int lane = id & 31, np = (id >> 5) & 7, kb = (id >> 8) & 3, k = id >> 10;
        int g = lane >> 2, tt = lane & 3;
        int o0 = np * 16 + g, o1 = o0 + 8, c = kb * 16 + 2 * tt;
        const float* W = W2 + (size_t)k * HIDn * H1n;
        uint4 v;
        v.x = pk(W[(size_t)o0 * H1n + c],     W[(size_t)o0 * H1n + c + 1]);
        v.y = pk(W[(size_t)o0 * H1n + c + 8], W[(size_t)o0 * H1n + c + 9]);
        v.z = pk(W[(size_t)o1 * H1n + c],     W[(size_t)o1 * H1n + c + 1]);
        v.w = pk(W[(size_t)o1 * H1n + c + 8], W[(size_t)o1 * H1n + c + 9]);
        w2F[id] = v;
    } else {
        int id = (bid - 2512) * 256 + tid;
        int lane = id & 31, np = (id >> 5) & 1, kb = (id >> 6) & 7, k = id >> 9;
        int g = lane >> 2, tt = lane & 3;
        int o0 = np * 16 + g, o1 = o0 + 8, c = kb * 16 + 2 * tt;
        const float* W = W3 + (size_t)k * Ln * HIDn;
        uint4 v;
        v.x = pk(W[(size_t)o0 * HIDn + c],     W[(size_t)o0 * HIDn + c + 1]);
        v.y = pk(W[(size_t)o0 * HIDn + c + 8], W[(size_t)o0 * HIDn + c + 9]);
        v.z = pk(W[(size_t)o1 * HIDn + c],     W[(size_t)o1 * HIDn + c + 1]);
        v.w = pk(W[(size_t)o1 * HIDn + c + 8], W[(size_t)o1 * HIDn + c + 9]);
        w3F[id] = v;
    }
}

// ================= main fused kernel: 128 threads, 4 warps, 4 CTAs/SM =================
__global__ __launch_bounds__(128, 4)
void fused_main(const int* __restrict__ ycls, const float* __restrict__ pr0,
                const float* __restrict__ pr1, float* __restrict__ out)
{
    extern __shared__ char smb[];
    const u32 smu = smem_u32(smb);
    const int k     = blockIdx.y;
    const int jtile = blockIdx.x;
    const int jbase = jtile * 128;
    const int b0    = jtile * 2;
    const int tid   = threadIdx.x;
    const int lane  = tid & 31;
    const int warp  = tid >> 5;
    const int g     = lane >> 2;
    const int tt    = lane & 3;

    // ---- cp.async: W2 + W3 group; then W1 half-chunk 0 ----
    {
        const uint4* w2k = w2F + (size_t)k * 1024;
        const uint4* w3k = w3F + (size_t)k * 512;
        #pragma unroll
        for (int i = 0; i < 8; i++) CP16(smu + W2S + (tid + i * 128) * 16, w2k + tid + i * 128);
        #pragma unroll
        for (int i = 0; i < 4; i++) CP16(smu + W3S + (tid + i * 128) * 16, w3k + tid + i * 128);
        CP_COMMIT();
    }
    const uint4* w1k = w1F + (size_t)k * 4096;
    {
        #pragma unroll
        for (int i = 0; i < 4; i++) CP16(smu + RING0 + (tid + i * 128) * 16, w1k + tid + i * 128);
        CP_COMMIT();
    }

    // ================= Stage A: M=32/warp, N=64, K=512 (8 half-chunks of 4 kb) =================
    const int R0 = jtile * 8 + warp * 2, R1 = R0 + 1;
    float accA[8][2][4];
    #pragma unroll
    for (int n = 0; n < 8; n++)
        #pragma unroll
        for (int r = 0; r < 2; r++)
            #pragma unroll
            for (int q = 0; q < 4; q++) accA[n][r][q] = 0.f;

    uint4 aA = xF[((size_t)R0 * 32 + 0) * 32 + lane];
    uint4 aB = xF[((size_t)R1 * 32 + 0) * 32 + lane];

    for (int hc = 0; hc < 8; hc++) {
        CP_WAIT(0);                              // current buf (hc&1) loaded
        __syncthreads();                         // all warps done reading buf being overwritten
        if (hc < 7) {
            u32 dst = smu + ((hc + 1) & 1) * 8192;
            const uint4* src = w1k + (hc + 1) * 512;
            #pragma unroll
            for (int i = 0; i < 4; i++) CP16(dst + (tid + i * 128) * 16, src + tid + i * 128);
            CP_COMMIT();
        }
        const char* rb = smb + (hc & 1) * 8192;
        #pragma unroll
        for (int q = 0; q < 4; q++) {
            int kb = hc * 4 + q;
            uint4 nA = aA, nB = aB;
            if (kb < 31) {
                nA = xF[((size_t)R0 * 32 + kb + 1) * 32 + lane];
                nB = xF[((size_t)R1 * 32 + kb + 1) * 32 + lane];
            }
            #pragma unroll
            for (int np = 0; np < 4; np++) {
                uint4 bv = *(const uint4*)(rb + ((q * 4 + np) * 32 + lane) * 16);
                mma_bf16(accA[2 * np][0],     aA, bv.x, bv.y);
                mma_bf16(accA[2 * np][1],     aB, bv.x, bv.y);
                mma_bf16(accA[2 * np + 1][0], aA, bv.z, bv.w);
                mma_bf16(accA[2 * np + 1][1], aB, bv.z, bv.w);
            }
            aA = nA; aB = nB;
        }
    }
    __syncthreads();                             // ring fully dead

    // ---- prototypes -> ring region via cp.async (overlaps B+C) ----
    {
        const float* p0k = pr0 + (size_t)k * Ln * Pn;
        const float* p1k = pr1 + (size_t)k * Ln * Pn;
        #pragma unroll
        for (int i = 0; i < 4; i++) {
            CP16(smu + RING0 + (tid + i * 128) * 16, p0k + (tid + i * 128) * 4);
            CP16(smu + RING1 + (tid + i * 128) * 16, p1k + (tid + i * 128) * 4);
        }
        CP_COMMIT();
    }

    // ---- h1 A-frags in registers ----
    uint4 h1f[2][4];                             // [rt][kb] over K=64
    #pragma unroll
    for (int rt = 0; rt < 2; rt++)
        #pragma unroll
        for (int kb = 0; kb < 4; kb++)
            h1f[rt][kb] = dfrag_to_afrag(accA[2 * kb][rt], accA[2 * kb + 1][rt]);

    // ================= Stages B+C fused: 8 N=16 slices, h2 never in smem =================
    float accC[4][2][4];
    #pragma unroll
    for (int n = 0; n < 4; n++)
        #pragma unroll
        for (int r = 0; r < 2; r++)
            #pragma unroll
            for (int q = 0; q < 4; q++) accC[n][r][q] = 0.f;

    #pragma unroll
    for (int s = 0; s < 8; s++) {
        // ---- stage B slice: N=16 (h2 cols [16s,16s+16)), K=64 ----
        float accB[2][2][4];
        #pragma unroll
        for (int n = 0; n < 2; n++)
            #pragma unroll
            for (int r = 0; r < 2; r++)
                #pragma unroll
                for (int q = 0; q < 4; q++) accB[n][r][q] = 0.f;
        #pragma unroll
        for (int kb = 0; kb < 4; kb++) {
            uint4 bv = *(const uint4*)(smb + W2S + ((kb * 8 + s) * 32 + lane) * 16);
            #pragma unroll
            for (int rt = 0; rt < 2; rt++) {
                mma_bf16(accB[0][rt], h1f[rt][kb], bv.x, bv.y);
                mma_bf16(accB[1][rt], h1f[rt][kb], bv.z, bv.w);
            }
        }
        // ---- pack slice as stage-C A-frag (K-chunk s) and accumulate C ----
        uint4 bw0 = *(const uint4*)(smb + W3S + ((s * 2 + 0) * 32 + lane) * 16);
        uint4 bw1 = *(const uint4*)(smb + W3S + ((s * 2 + 1) * 32 + lane) * 16);
        #pragma unroll
        for (int rt = 0; rt < 2; rt++) {
            uint4 af = dfrag_to_afrag(accB[0][rt], accB[1][rt]);
            mma_bf16(accC[0][rt], af, bw0.x, bw0.y);
            mma_bf16(accC[1][rt], af, bw0.z, bw0.w);
            mma_bf16(accC[2][rt], af, bw1.x, bw1.y);
            mma_bf16(accC[3][rt], af, bw1.z, bw1.w);
        }
    }

    CP_WAIT(0);                                  // protos landed
    __syncthreads();                             // all warps done with W2/W3; protos visible

    // ---- epilogue C: tanh, distances, clip, logits, per-(k,b) sums ----
    {
        const float* ps0 = (const float*)(smb + RING0);   // [32][64] fp32
        const float* ps1 = (const float*)(smb + RING1);
        float* ers  = (float*)(smb + W2S);
        float* er1s = ers + 128;
        #pragma unroll
        for (int rt = 0; rt < 2; rt++) {
            #pragma unroll
            for (int half = 0; half < 2; half++) {
                int lr = warp * 32 + rt * 16 + g + half * 8;
                int p  = (jbase + lr) & 63;
                float d0 = 0.f, d1 = 0.f;
                #pragma unroll
                for (int n0 = 0; n0 < 4; n0++) {
                    int c0 = n0 * 8 + 2 * tt, c1 = c0 + 1;
                    float v0 = tanh_fast(accC[n0][rt][half * 2 + 0]);
                    float v1 = tanh_fast(accC[n0][rt][half * 2 + 1]);
                    float q;
                    q = v0 - ps0[c0 * 64 + p]; d0 += q * q;
                    q = v1 - ps0[c1 * 64 + p]; d0 += q * q;
                    q = v0 - ps1[c0 * 64 + p]; d1 += q * q;
                    q = v1 - ps1[c1 * 64 + p]; d1 += q * q;
                }
                d0 += __shfl_xor_sync(0xFFFFFFFFu, d0, 1);
                d0 += __shfl_xor_sync(0xFFFFFFFFu, d0, 2);
                d1 += __shfl_xor_sync(0xFFFFFFFFu, d1, 1);
                d1 += __shfl_xor_sync(0xFFFFFFFFu, d1, 2);
                if (tt == 0) {
                    float er  = fminf(fmaxf(d0 * REDV, -CLIPV), CLIPV);
                    float er1 = fminf(fmaxf(d1 * REDV, -CLIPV), CLIPV);
                    int b = b0 + (lr >> 6);
                    out[((size_t)b * Kn + k) * Pn + p] = er;
                    out[(size_t)Bn * Kn * Pn + ((size_t)b * Kn + k) * Pn + p] = er1;
                    ers[lr]  = er;
                    er1s[lr] = er1;
                }
            }
        }
    }
    __syncthreads();
    if (tid < 4) {
        int bb = tid & 1;
        const float* src = (float*)(smb + W2S) + ((tid < 2) ? 0 : 128);
        float s = 0.f;
        #pragma unroll
        for (int p = 0; p < 64; p++) s += src[bb * 64 + p];
        if (tid < 2) f_dev[k * Bn + b0 + bb]  = s;
        else         f1_dev[k * Bn + b0 + bb] = s;
    }
    __syncthreads();

    // ---- last-CTA finalize: pull/push ----
    __threadfence();
    __shared__ u32 s_is_last;
    if (tid == 0) {
        u32 old = atomicAdd(&done_ctr, 1u);
        s_is_last = (old == gridDim.x * gridDim.y - 1) ? 1u : 0u;
    }
    __syncthreads();
    if (s_is_last) {
        __threadfence();
        float* s_pull = (float*)smb;
        float* s_push = s_pull + 128;
        float pull = 0.f, push = 0.f;
        if (tid < Kn) {
            float se = 0.f, sc = 0.f;
            int ne = 0, nc = 0;
            #pragma unroll 8
            for (int b = 0; b < Bn; b++) {
                float fv  = __ldcg(&f_dev[tid * Bn + b]);
                float f1v = __ldcg(&f1_dev[tid * Bn + b]);
                if (ycls[b] == tid) { se += f1v; ne++; }
                else if (fv < PUSHT) { sc += fv; nc++; }
            }
            if (ne > 0) pull = se / (float)ne;
            if (nc > 0) push = sc / (float)nc;
        }
        s_pull[tid] = pull;
        s_push[tid] = push;
        __syncthreads();
        for (int s = 64; s > 0; s >>= 1) {
            if (tid < s) { s_pull[tid] += s_pull[tid + s]; s_push[tid] += s_push[tid + s]; }
            __syncthreads();
        }
        if (tid == 0) {
            size_t base = (size_t)2 * Bn * Kn * Pn;
            out[base]     = s_pull[0];
            out[base + 1] = s_push[0];
            done_ctr = 0;   // deterministic across graph replays
        }
    }
}

extern "C" void kernel_launch(void* const* d_in, const int* in_sizes, int n_in,
                              void* d_out, int out_size)
{
    const float* x    = (const float*)d_in[0];
    const int*   ycls = (const int*)  d_in[1];
    const float* W1   = (const float*)d_in[4];
    const float* W2   = (const float*)d_in[5];
    const float* W3   = (const float*)d_in[6];
    const float* pr0  = (const float*)d_in[7];
    const float* pr1  = (const float*)d_in[8];
    float* out = (float*)d_out;

    permute_all<<<2712, 256>>>(x, W1, W2, W3);

    cudaFuncSetAttribute(fused_main, cudaFuncAttributeMaxDynamicSharedMemorySize, SMEM_BYTES);
    fused_main<<<dim3(32, Kn), 128, SMEM_BYTES>>>(ycls, pr0, pr1, out);
}